// round 12
// baseline (speedup 1.0000x reference)
#include <cuda_runtime.h>
#include <cuda_bf16.h>
#include <cuda_fp16.h>
#include <cstdint>

// ---------------------------------------------------------------------------
// MetaCNNLSTM: conv1d(64->256,k9,same) + GN(8)+ReLU -> 3x LSTM(512) -> mean -> head(50)
// B=32, T=512.
// LSTM: 4 independent groups of 8 batches; 32 persistent blocks/group (16 cells).
// Compensated fp16 HMMA (3 passes), W-hi fragments in registers.
// NEW: two-level tree barrier (monotonic, no resets) + k-half-split h copy with
// per-half mbarriers so each warp's GEMM overlaps the other half's TMA.
// ---------------------------------------------------------------------------

#define B_      32
#define CIN     64
#define T_      512
#define NF      256
#define GN_G    8
#define KW      9
#define H_      512
#define G4H     2048
#define NCLS    50

#define NBLK    128            // 4 groups x 32 blocks
#define GRP     32
#define THR     256

// lstm dynamic smem layout (byte offsets from 1024-aligned base)
#define SM_WHI   0          // W hi: 64 rows x 64 chunks(16B) fp16, chunk^=(row&7)  65536
#define SM_WLO   65536      // W lo                                                 65536
#define SM_BH    131072     // h: [khalf(2)][img(2)][b(8)][512B]                    16384
#define SM_GSM   147456     // gates 2(k-half) x [64][10] fp32                       5120
#define SM_XGS   152576     // xg staging 2 x [8][64] fp32                           4096
#define SM_HSMH  156672     // h hi staging [8][16] fp16                              256
#define SM_HSML  156928     // h lo staging                                           256
#define SM_MBAR0 157184     // mbarrier 0 (h khalf0 + xg)
#define SM_MBAR1 157192     // mbarrier 1 (h khalf1)
#define SM_TOTAL 157200
#define SMEM_REQ (SM_TOTAL + 1024)

// xg HMMA kernel smem layout
#define XGS_AHI  0
#define XGS_ALO  32768
#define XGS_BHI  65536
#define XGS_BLO  98304
#define XG_SMEM_TOTAL 131072
#define XG_SMEM_REQ (XG_SMEM_TOTAL + 1024)

// ---- global scratch ----
__device__ float g_conv[B_ * NF * T_];
__device__ float g_bufA[B_ * T_ * H_];
__device__ float g_bufB[B_ * T_ * H_];
// [t][blk(128)][b_local(8)][gate*16+cl]  -- 2KB per (t, blk)
__device__ __align__(4096) float g_xg[T_ * NBLK * 8 * 64];
// h: [group(4)][khalf(2)][img(2)][b(8)][512B] = 4 x 16KB
__device__ __align__(1024) __half g_h2[4 * 2 * 2 * 8 * 256];
// two-level barrier: monotonic counters, padded 128B apart
__device__ unsigned g_sub[4 * 4 * 32];    // [group][sub(4)] * 32 pad
__device__ unsigned g_top[4 * 32];
__device__ unsigned g_gen2[4 * 32];

// ---------------------------------------------------------------------------
// helpers
// ---------------------------------------------------------------------------
__device__ __forceinline__ float sigmoidf(float x) { return 1.0f / (1.0f + __expf(-x)); }
__device__ __forceinline__ float tanh_fast(float x) { return 1.0f - 2.0f / (1.0f + __expf(2.0f * x)); }

__device__ __forceinline__ unsigned ld_acquire(unsigned* p) {
    unsigned v;
    asm volatile("ld.acquire.gpu.global.u32 %0, [%1];" : "=r"(v) : "l"(p) : "memory");
    return v;
}
__device__ __forceinline__ void st_release(unsigned* p, unsigned v) {
    asm volatile("st.release.gpu.global.u32 [%0], %1;" :: "l"(p), "r"(v) : "memory");
}
__device__ __forceinline__ uint32_t smem_u32(const void* p) {
    uint32_t a;
    asm("{ .reg .u64 t; cvta.to.shared.u64 t, %1; cvt.u32.u64 %0, t; }" : "=r"(a) : "l"(p));
    return a;
}
__device__ __forceinline__ uint32_t split_pair_h(float a, float b, uint32_t& lo_out) {
    __half ha = __float2half_rn(a), hb = __float2half_rn(b);
    float la = a - __half2float(ha);
    float lb = b - __half2float(hb);
    __half2 lo2 = __halves2half2(__float2half_rn(la), __float2half_rn(lb));
    __half2 hi2 = __halves2half2(ha, hb);
    lo_out = *reinterpret_cast<uint32_t*>(&lo2);
    return *reinterpret_cast<uint32_t*>(&hi2);
}
__device__ __forceinline__ void sts128(uint32_t addr, uint4 v) {
    asm volatile("st.shared.v4.b32 [%0], {%1,%2,%3,%4};"
                 :: "r"(addr), "r"(v.x), "r"(v.y), "r"(v.z), "r"(v.w) : "memory");
}
__device__ __forceinline__ void ldmatrix4(uint32_t& r0, uint32_t& r1, uint32_t& r2, uint32_t& r3, uint32_t addr) {
    asm volatile("ldmatrix.sync.aligned.m8n8.x4.shared.b16 {%0,%1,%2,%3}, [%4];"
                 : "=r"(r0), "=r"(r1), "=r"(r2), "=r"(r3) : "r"(addr));
}
__device__ __forceinline__ void ldmatrix2(uint32_t& r0, uint32_t& r1, uint32_t addr) {
    asm volatile("ldmatrix.sync.aligned.m8n8.x2.shared.b16 {%0,%1}, [%2];"
                 : "=r"(r0), "=r"(r1) : "r"(addr));
}
__device__ __forceinline__ void mma16816h(float* c, const uint32_t* a, uint32_t b0, uint32_t b1) {
    asm volatile("mma.sync.aligned.m16n8k16.row.col.f32.f16.f16.f32 "
                 "{%0,%1,%2,%3}, {%4,%5,%6,%7}, {%8,%9}, {%0,%1,%2,%3};"
                 : "+f"(c[0]), "+f"(c[1]), "+f"(c[2]), "+f"(c[3])
                 : "r"(a[0]), "r"(a[1]), "r"(a[2]), "r"(a[3]), "r"(b0), "r"(b1));
}

#define MBAR_WAIT(mbar, ph) do {                                                   \
    uint32_t _done;                                                                \
    asm volatile("{\n\t.reg .pred p;\n\t"                                          \
        "mbarrier.try_wait.parity.acquire.cta.shared::cta.b64 p, [%1], %2;\n\t"    \
        "selp.b32 %0, 1, 0, p;\n\t}"                                               \
        : "=r"(_done) : "r"(mbar), "r"(ph) : "memory");                            \
    if (!_done) {                                                                  \
        asm volatile("{\n\t.reg .pred P1;\n\t"                                     \
            "WL_%=:\n\t"                                                           \
            "mbarrier.try_wait.parity.acquire.cta.shared::cta.b64 P1, [%0], %1, 0x989680;\n\t" \
            "@P1 bra.uni WD_%=;\n\t"                                               \
            "bra.uni WL_%=;\n\t"                                                   \
            "WD_%=:\n\t}"                                                          \
            :: "r"(mbar), "r"(ph) : "memory");                                     \
    }                                                                              \
} while (0)

// ---------------------------------------------------------------------------
// conv1d
// ---------------------------------------------------------------------------
__global__ void conv_kernel(const float* __restrict__ x, const float* __restrict__ w) {
    int bf = blockIdx.x;
    int b = bf >> 8, f = bf & 255;
    __shared__ float wsh[CIN * KW];
    for (int e = threadIdx.x; e < CIN * KW; e += blockDim.x)
        wsh[e] = w[f * CIN * KW + e];
    __syncthreads();
    const float* xb = x + b * CIN * T_;
    #pragma unroll
    for (int tt = 0; tt < 4; ++tt) {
        int t = tt * 128 + threadIdx.x;
        float acc = 0.f;
        for (int c = 0; c < CIN; ++c) {
            const float* xr = xb + c * T_;
            const float* wr = wsh + c * KW;
            #pragma unroll
            for (int k = 0; k < KW; ++k) {
                int ti = t + k - 4;
                if (ti >= 0 && ti < T_) acc += xr[ti] * wr[k];
            }
        }
        g_conv[(b * NF + f) * T_ + t] = acc;
    }
}

// ---------------------------------------------------------------------------
// fused GroupNorm (stats + apply + ReLU + transpose -> g_bufA)
// ---------------------------------------------------------------------------
__global__ void gn_kernel(const float* __restrict__ gamma, const float* __restrict__ beta) {
    int bg = blockIdx.x;
    int b = bg >> 3, g = bg & 7;
    const float* base = g_conv + (b * NF + g * 32) * T_;
    float s = 0.f, ss = 0.f;
    for (int e = threadIdx.x; e < 32 * T_; e += blockDim.x) {
        float v = base[e];
        s += v; ss += v * v;
    }
    __shared__ float sh_s[256], sh_q[256];
    sh_s[threadIdx.x] = s; sh_q[threadIdx.x] = ss;
    __syncthreads();
    for (int st = 128; st > 0; st >>= 1) {
        if (threadIdx.x < st) {
            sh_s[threadIdx.x] += sh_s[threadIdx.x + st];
            sh_q[threadIdx.x] += sh_q[threadIdx.x + st];
        }
        __syncthreads();
    }
    __shared__ float sh_mu, sh_rs;
    if (threadIdx.x == 0) {
        float n = 32.0f * (float)T_;
        float mu = sh_s[0] / n;
        float var = sh_q[0] / n - mu * mu;
        sh_mu = mu;
        sh_rs = rsqrtf(var + 1e-5f);
    }
    __syncthreads();
    float mu = sh_mu, rs = sh_rs;
    for (int e = threadIdx.x; e < 32 * T_; e += blockDim.x) {
        int cl = e >> 9, t = e & 511;
        int f = g * 32 + cl;
        float v = (base[e] - mu) * rs * gamma[f] + beta[f];
        v = fmaxf(v, 0.f);
        g_bufA[(b * T_ + t) * NF + f] = v;
    }
}

// ---------------------------------------------------------------------------
// xg projection GEMM on HMMA (compensated fp16, 3 passes).
// output: g_xg[((t*128 + blk)*8 + b_local)*64 + gate*16 + cl]
//   blk = (b>>3)*32 + (cell>>4), b_local = b&7, cl = cell&15
// ---------------------------------------------------------------------------
__global__ __launch_bounds__(256) void xg_hmma_kernel(int layer,
                                                      const float* __restrict__ Wih,
                                                      const float* __restrict__ bias,
                                                      int Din) {
    const float* X = (layer == 2) ? g_bufB : g_bufA;
    extern __shared__ char smraw[];
    uint32_t rawa = smem_u32(smraw);
    uint32_t base = (rawa + 1023u) & ~1023u;
    uint32_t aHI = base + XGS_AHI;
    uint32_t aLO = base + XGS_ALO;
    uint32_t bHI = base + XGS_BHI;
    uint32_t bLO = base + XGS_BLO;

    const int tid = threadIdx.x;
    const int wid = tid >> 5, lane = tid & 31;
    const int n0 = blockIdx.x * 128, m0 = blockIdx.y * 128;

    const int wm = wid & 1, wn = wid >> 1;
    const int lrow = lane & 15, lk = lane >> 4;
    const int bcs = (lane >> 3) & 1;

    const int r = tid & 127, hf = tid >> 7;
    const int mg = m0 + r;
    const float* asrc0 = X + ((size_t)(mg & 31) * T_ + (mg >> 5)) * Din + hf * 64;
    const float* bsrc0 = Wih + (size_t)(n0 + r) * Din + hf * 64;
    const uint32_t stoff0 = (uint32_t)(r * 256);

    float acc[4][4][4];
    #pragma unroll
    for (int mi = 0; mi < 4; ++mi)
        #pragma unroll
        for (int ni = 0; ni < 4; ++ni)
            #pragma unroll
            for (int q = 0; q < 4; ++q) acc[mi][ni][q] = 0.f;

    const int nchunks = Din >> 7;
    for (int kc = 0; kc < nchunks; ++kc) {
        const float* asrc = asrc0 + kc * 128;
        const float* bsrc = bsrc0 + kc * 128;
        #pragma unroll
        for (int j = 0; j < 8; ++j) {
            int c = hf * 8 + j;
            uint32_t off = stoff0 + (uint32_t)(((c ^ (r & 7))) << 4);
            {
                float4 f0 = *(const float4*)(asrc + j * 8);
                float4 f1 = *(const float4*)(asrc + j * 8 + 4);
                uint4 vh, vl;
                vh.x = split_pair_h(f0.x, f0.y, vl.x);
                vh.y = split_pair_h(f0.z, f0.w, vl.y);
                vh.z = split_pair_h(f1.x, f1.y, vl.z);
                vh.w = split_pair_h(f1.z, f1.w, vl.w);
                sts128(aHI + off, vh);
                sts128(aLO + off, vl);
            }
            {
                float4 f0 = *(const float4*)(bsrc + j * 8);
                float4 f1 = *(const float4*)(bsrc + j * 8 + 4);
                uint4 vh, vl;
                vh.x = split_pair_h(f0.x, f0.y, vl.x);
                vh.y = split_pair_h(f0.z, f0.w, vl.y);
                vh.z = split_pair_h(f1.x, f1.y, vl.z);
                vh.w = split_pair_h(f1.z, f1.w, vl.w);
                sts128(bHI + off, vh);
                sts128(bLO + off, vl);
            }
        }
        __syncthreads();

        #pragma unroll
        for (int s = 0; s < 8; ++s) {
            uint32_t ahf[4][4], alf[4][4], bhf[4][2], blf[4][2];
            #pragma unroll
            for (int mi = 0; mi < 4; ++mi) {
                int rowA = wm * 64 + mi * 16 + lrow;
                uint32_t aoff = (uint32_t)(rowA * 256 + (((2 * s + lk) ^ (rowA & 7)) << 4));
                ldmatrix4(ahf[mi][0], ahf[mi][1], ahf[mi][2], ahf[mi][3], aHI + aoff);
                ldmatrix4(alf[mi][0], alf[mi][1], alf[mi][2], alf[mi][3], aLO + aoff);
            }
            #pragma unroll
            for (int ni = 0; ni < 4; ++ni) {
                int rowB = wn * 32 + ni * 8 + (lane & 7);
                uint32_t boff = (uint32_t)(rowB * 256 + (((2 * s + bcs) ^ (rowB & 7)) << 4));
                ldmatrix2(bhf[ni][0], bhf[ni][1], bHI + boff);
                ldmatrix2(blf[ni][0], blf[ni][1], bLO + boff);
            }
            #pragma unroll
            for (int mi = 0; mi < 4; ++mi)
                #pragma unroll
                for (int ni = 0; ni < 4; ++ni) {
                    mma16816h(acc[mi][ni], ahf[mi], bhf[ni][0], bhf[ni][1]);
                    mma16816h(acc[mi][ni], ahf[mi], blf[ni][0], blf[ni][1]);
                    mma16816h(acc[mi][ni], alf[mi], bhf[ni][0], bhf[ni][1]);
                }
        }
        __syncthreads();
    }

    #pragma unroll
    for (int mi = 0; mi < 4; ++mi) {
        #pragma unroll
        for (int ni = 0; ni < 4; ++ni) {
            int cb = n0 + wn * 32 + ni * 8 + (lane & 3) * 2;
            int gate = cb >> 9, cell = cb & 511;
            int cblk = cell >> 4, cl = cell & 15;
            float bz0 = bias[cb], bz1 = bias[cb + 1];
            #pragma unroll
            for (int hrow = 0; hrow < 2; ++hrow) {
                int row = m0 + wm * 64 + mi * 16 + (lane >> 2) + hrow * 8;
                int t = row >> 5, b = row & 31;
                int blk = (b >> 3) * 32 + cblk;
                float2 v = make_float2(acc[mi][ni][hrow * 2 + 0] + bz0,
                                       acc[mi][ni][hrow * 2 + 1] + bz1);
                *(float2*)&g_xg[(((size_t)t * NBLK + blk) * 8 + (b & 7)) * 64 + gate * 16 + cl] = v;
            }
        }
    }
}

// ---------------------------------------------------------------------------
// persistent HMMA LSTM: 4 groups x 32 blocks. Block bx: group g=bx>>5 (batches
// g*8..+8), cells (bx&31)*16..+16. 8 warps = 4(m16) x 2(k-half).
// k-half-split h copy (per-half mbarriers) + two-level tree barrier.
// ---------------------------------------------------------------------------
__global__ __launch_bounds__(THR, 1) void lstm_kernel(const float* __restrict__ Whh,
                                                      const float* __restrict__ xg,
                                                      float* __restrict__ Y) {
    extern __shared__ char smraw[];
    uint32_t rawa = smem_u32(smraw);
    uint32_t base = (rawa + 1023u) & ~1023u;
    char* sbase = smraw + (base - rawa);
    uint32_t wHI  = base + SM_WHI;
    uint32_t wLO  = base + SM_WLO;
    uint32_t bBH  = base + SM_BH;
    float*   gsm  = (float*)(sbase + SM_GSM);
    float*   xgs  = (float*)(sbase + SM_XGS);
    __half*  hsmh = (__half*)(sbase + SM_HSMH);
    __half*  hsml = (__half*)(sbase + SM_HSML);
    uint32_t mbar0 = base + SM_MBAR0;
    uint32_t mbar1 = base + SM_MBAR1;
    uint32_t xgs_a = base + SM_XGS;

    const int tid = threadIdx.x;
    const int bx = blockIdx.x;
    const int g  = bx >> 5;            // batch group (0..3)
    const int ci = bx & 31;            // cell-block index (0..31)
    const int c0 = ci * 16;
    const int wid = tid >> 5, lane = tid & 31;

    unsigned* subp = &g_sub[(g * 4 + (ci >> 3)) * 32];
    unsigned* topp = &g_top[g * 32];
    unsigned* genp = &g_gen2[g * 32];
    unsigned mygen = *((volatile unsigned*)genp);

    if (tid == 0) {
        asm volatile("mbarrier.init.shared.b64 [%0], %1;" :: "r"(mbar0), "r"(1u) : "memory");
        asm volatile("mbarrier.init.shared.b64 [%0], %1;" :: "r"(mbar1), "r"(1u) : "memory");
    }

    // --- stage W tile: 64 rows x 64 chunks(16B), fp32 -> fp16 hi/lo, chunk^=(row&7) ---
    #pragma unroll
    for (int i = 0; i < 16; ++i) {
        int gg = tid + i * 256;           // 4096 chunks
        int r = gg >> 6, k16 = gg & 63;
        int j = (r & 3) * 512 + c0 + (r >> 2);
        const float* src = Whh + (size_t)j * 512 + k16 * 8;
        float4 f0 = *(const float4*)(src);
        float4 f1 = *(const float4*)(src + 4);
        uint4 vh, vl;
        vh.x = split_pair_h(f0.x, f0.y, vl.x);
        vh.y = split_pair_h(f0.z, f0.w, vl.y);
        vh.z = split_pair_h(f1.x, f1.y, vl.z);
        vh.w = split_pair_h(f1.z, f1.w, vl.w);
        uint32_t off = (uint32_t)((r << 10) + (((k16 ^ (r & 7))) << 4));
        sts128(wHI + off, vh);
        sts128(wLO + off, vl);
    }

    // --- zero this block's chunks (global 2ci, 2ci+1) of both images ---
    // g_h2 layout: [group][khalf][img][b][512B]; chunk c local cL=c&31, kh=c>>5
    if (tid < 32) {
        int q = tid & 1, b = (tid >> 1) & 7, img = tid >> 4;
        int c = 2 * ci + q, kh = c >> 5, cL = c & 31;
        uint32_t off = (uint32_t)((((g * 2 + kh) * 2 + img) * 8 + b) * 512 + (((cL ^ (b & 7))) << 4));
        *(uint4*)((char*)g_h2 + off) = make_uint4(0, 0, 0, 0);
    }
    __syncthreads();

    // GEMM thread mapping: 4m x 2k
    const int wm = wid & 3, wk = wid >> 2;
    const int lrow = lane & 15, lk = lane >> 4;
    const uint32_t arowoff = (uint32_t)(((wm * 16 + lrow) << 10));
    const int ax7 = lrow & 7;

    // --- hoist W-hi fragments (this warp's k-half) into registers ---
    uint32_t AH[16][4];
    #pragma unroll
    for (int ks = 0; ks < 16; ++ks) {
        int ch = (wk * 16 + ks) * 2 + lk;
        uint32_t aoff = (uint32_t)(((ch ^ ax7)) << 4);
        ldmatrix4(AH[ks][0], AH[ks][1], AH[ks][2], AH[ks][3], wHI + arowoff + aoff);
    }

    // --- prologue: prefetch xg(0) (mbar0) + initial two-level barrier ---
    if (tid == 0) {
        asm volatile("mbarrier.arrive.expect_tx.shared.b64 _, [%0], %1;"
                     :: "r"(mbar0), "r"(2048u) : "memory");
        asm volatile("cp.async.bulk.shared::cluster.global.mbarrier::complete_tx::bytes "
                     "[%0], [%1], %2, [%3];"
                     :: "r"(xgs_a), "l"((const char*)(xg + (size_t)bx * 512)), "r"(2048u), "r"(mbar0) : "memory");
        __threadfence();
        unsigned a = atomicAdd(subp, 1u);
        bool rel = false;
        if ((a & 7u) == 7u) {
            unsigned b2 = atomicAdd(topp, 1u);
            if ((b2 & 3u) == 3u) { st_release(genp, mygen + 1u); rel = true; }
        }
        if (!rel) { while (ld_acquire(genp) == mygen) {} }
    }
    mygen++;
    __syncthreads();

    // B-frag addressing (8 batch rows, 512B row stride, per-khalf region)
    const int brow = lane & 7;
    const uint32_t bregion = bBH + (uint32_t)(wk * 8192);
    const uint32_t browoff = (uint32_t)(brow * 512);
    const int bx7 = brow;
    const int bcs = (lane >> 3) & 1;

    // activation mapping: cl = tid>>3 (0..15), b_local = tid&7  (tid < 128)
    const int cl = tid >> 3;
    const int bb = tid & 7;
    float cst = 0.f;

    const char* hsrc = (const char*)g_h2 + g * 16384;

    for (int t = 0; t < T_; ++t) {
        // 1. bulk copies: h khalf1 -> mbar1 (8KB), h khalf0 + xg(t+1) -> mbar0
        if (tid == 0) {
            asm volatile("mbarrier.arrive.expect_tx.shared.b64 _, [%0], %1;"
                         :: "r"(mbar1), "r"(8192u) : "memory");
            asm volatile("cp.async.bulk.shared::cluster.global.mbarrier::complete_tx::bytes "
                         "[%0], [%1], %2, [%3];"
                         :: "r"(bBH + 8192u), "l"(hsrc + 8192), "r"(8192u), "r"(mbar1) : "memory");
            unsigned txb = 8192u + ((t + 1 < T_) ? 2048u : 0u);
            asm volatile("mbarrier.arrive.expect_tx.shared.b64 _, [%0], %1;"
                         :: "r"(mbar0), "r"(txb) : "memory");
            asm volatile("cp.async.bulk.shared::cluster.global.mbarrier::complete_tx::bytes "
                         "[%0], [%1], %2, [%3];"
                         :: "r"(bBH), "l"(hsrc), "r"(8192u), "r"(mbar0) : "memory");
            if (t + 1 < T_) {
                const char* xsrc = (const char*)(xg + (((size_t)(t + 1) * NBLK + bx) * 512));
                asm volatile("cp.async.bulk.shared::cluster.global.mbarrier::complete_tx::bytes "
                             "[%0], [%1], %2, [%3];"
                             :: "r"(xgs_a + (((t + 1) & 1) ? 2048u : 0u)), "l"(xsrc), "r"(2048u), "r"(mbar0) : "memory");
            }
        }
        // each warp waits only on its own k-half's mbarrier
        if (wk == 0) { MBAR_WAIT(mbar0, (uint32_t)((t + 1) & 1)); }
        else         { MBAR_WAIT(mbar1, (uint32_t)(t & 1)); }

        // 2. GEMM: 16 k-steps (this warp's half), 3 accumulator chains
        float acc_a[4] = {0.f, 0.f, 0.f, 0.f};
        float acc_b[4] = {0.f, 0.f, 0.f, 0.f};
        float acc_c[4] = {0.f, 0.f, 0.f, 0.f};
        #pragma unroll
        for (int ks = 0; ks < 16; ++ks) {
            int chA = (wk * 16 + ks) * 2 + lk;
            int chB = (ks * 2 + bcs) & 31;            // local chunk within k-half
            uint32_t aoff = (uint32_t)(((chA ^ ax7)) << 4);
            uint32_t boff = (uint32_t)(((chB ^ bx7)) << 4);
            uint32_t al0, al1, al2, al3;
            uint32_t bh0, bh1, bl0, bl1;
            ldmatrix4(al0, al1, al2, al3, wLO + arowoff + aoff);
            ldmatrix2(bh0, bh1, bregion + browoff + boff);
            ldmatrix2(bl0, bl1, bregion + 4096u + browoff + boff);
            mma16816h(acc_a, AH[ks], bh0, bh1);
            mma16816h(acc_b, AH[ks], bl0, bl1);
            uint32_t alr[4] = {al0, al1, al2, al3};
            mma16816h(acc_c, alr, bh0, bh1);
        }

        // 3. combine + store per-k-half gates to gsm[wk] ([64][10])
        {
            int r0 = wm * 16 + (lane >> 2);
            int cb = (lane & 3) * 2;
            float* gk = gsm + wk * 640;
            float s0 = acc_a[0] + acc_b[0] + acc_c[0];
            float s1 = acc_a[1] + acc_b[1] + acc_c[1];
            float s2 = acc_a[2] + acc_b[2] + acc_c[2];
            float s3 = acc_a[3] + acc_b[3] + acc_c[3];
            *(float2*)&gk[r0 * 10 + cb]       = make_float2(s0, s1);
            *(float2*)&gk[(r0 + 8) * 10 + cb] = make_float2(s2, s3);
        }
        __syncthreads();

        // 4. activation: thread (cl, bb); sum k-halves; c-state in reg
        if (tid < 128) {
            const float* xb2 = xgs + ((t & 1) ? 512 : 0) + bb * 64;
            int r = cl * 4;
            float gi = gsm[(r + 0) * 10 + bb] + gsm[640 + (r + 0) * 10 + bb] + xb2[cl];
            float gf = gsm[(r + 1) * 10 + bb] + gsm[640 + (r + 1) * 10 + bb] + xb2[16 + cl];
            float gg = gsm[(r + 2) * 10 + bb] + gsm[640 + (r + 2) * 10 + bb] + xb2[32 + cl];
            float go = gsm[(r + 3) * 10 + bb] + gsm[640 + (r + 3) * 10 + bb] + xb2[48 + cl];
            float iv = sigmoidf(gi);
            float fv = sigmoidf(gf);
            float gv = tanh_fast(gg);
            float ov = sigmoidf(go);
            cst = fv * cst + iv * gv;
            float hv = ov * tanh_fast(cst);
            __half hh = __float2half_rn(hv);
            hsmh[bb * 16 + cl] = hh;
            hsml[bb * 16 + cl] = __float2half_rn(hv - __half2float(hh));
            Y[((size_t)(g * 8 + bb) * T_ + t) * H_ + c0 + cl] = hv;
        }
        __syncthreads();

        // 5. publish h chunks (global 2ci, 2ci+1) of both images
        if (tid < 32) {
            int q = tid & 1, b = (tid >> 1) & 7, img = tid >> 4;
            const __half* s = img ? hsml : hsmh;
            uint4 v = *(const uint4*)(s + b * 16 + q * 8);
            int c = 2 * ci + q, kh = c >> 5, cL = c & 31;
            uint32_t off = (uint32_t)((((g * 2 + kh) * 2 + img) * 8 + b) * 512 + (((cL ^ (b & 7))) << 4));
            *(uint4*)((char*)g_h2 + off) = v;
        }

        // 6. two-level tree barrier (monotonic counters)
        __syncthreads();
        if (tid == 0) {
            __threadfence();
            unsigned a = atomicAdd(subp, 1u);
            bool rel = false;
            if ((a & 7u) == 7u) {
                unsigned b2 = atomicAdd(topp, 1u);
                if ((b2 & 3u) == 3u) { st_release(genp, mygen + 1u); rel = true; }
            }
            if (!rel) { while (ld_acquire(genp) == mygen) {} }
        }
        mygen++;
        __syncthreads();
    }
}

// ---------------------------------------------------------------------------
// mean over T + head GEMV
// ---------------------------------------------------------------------------
__global__ void pool_head_kernel(const float* __restrict__ head_w,
                                 const float* __restrict__ head_b,
                                 float* __restrict__ out) {
    int b = blockIdx.x;
    int h = threadIdx.x;
    __shared__ float feat[H_];
    const float* Yp = g_bufB + (size_t)b * T_ * H_;
    float s = 0.f;
    for (int t = 0; t < T_; ++t) s += Yp[t * H_ + h];
    feat[h] = s * (1.0f / (float)T_);
    __syncthreads();
    for (int cc = threadIdx.x; cc < NCLS; cc += blockDim.x) {
        float a = head_b[cc];
        const float* wr = head_w + cc * H_;
        for (int k = 0; k < H_; ++k) a += feat[k] * wr[k];
        out[b * NCLS + cc] = a;
    }
}

// ---------------------------------------------------------------------------
extern "C" void kernel_launch(void* const* d_in, const int* in_sizes, int n_in,
                              void* d_out, int out_size) {
    const float* x     = (const float*)d_in[0];
    const float* convw = (const float*)d_in[1];
    const float* gamma = (const float*)d_in[2];
    const float* beta  = (const float*)d_in[3];

    bool head_first = (in_sizes[4] == NCLS * H_);
    int o = head_first ? 6 : 4;
    const float* headw = (const float*)d_in[head_first ? 4 : 13];
    const float* headb = (const float*)d_in[head_first ? 5 : 14];
    const float* wih[3] = { (const float*)d_in[o + 0], (const float*)d_in[o + 3], (const float*)d_in[o + 6] };
    const float* whh[3] = { (const float*)d_in[o + 1], (const float*)d_in[o + 4], (const float*)d_in[o + 7] };
    const float* bb[3]  = { (const float*)d_in[o + 2], (const float*)d_in[o + 5], (const float*)d_in[o + 8] };

    static int smem_set = 0;
    if (!smem_set) {
        cudaFuncSetAttribute(lstm_kernel, cudaFuncAttributeMaxDynamicSharedMemorySize, SMEM_REQ);
        cudaFuncSetAttribute(xg_hmma_kernel, cudaFuncAttributeMaxDynamicSharedMemorySize, XG_SMEM_REQ);
        smem_set = 1;
    }

    void* xgsym = nullptr;   cudaGetSymbolAddress(&xgsym, g_xg);
    void* bufAsym = nullptr; cudaGetSymbolAddress(&bufAsym, g_bufA);
    void* bufBsym = nullptr; cudaGetSymbolAddress(&bufBsym, g_bufB);

    conv_kernel<<<B_ * NF, 128>>>(x, convw);
    gn_kernel<<<B_ * GN_G, 256>>>(gamma, beta);

    for (int layer = 1; layer <= 3; ++layer) {
        int din = (layer == 1) ? NF : H_;
        dim3 gg(G4H / 128, (B_ * T_) / 128);
        xg_hmma_kernel<<<gg, 256, XG_SMEM_REQ>>>(layer, wih[layer - 1], bb[layer - 1], din);
        float* yptr = (layer == 2) ? (float*)bufAsym : (float*)bufBsym;
        lstm_kernel<<<NBLK, THR, SMEM_REQ>>>(whh[layer - 1], (const float*)xgsym, yptr);
    }

    pool_head_kernel<<<B_, H_>>>(headw, headb, (float*)d_out);
}

// round 13
// speedup vs baseline: 1.0259x; 1.0259x over previous
#include <cuda_runtime.h>
#include <cuda_bf16.h>
#include <cuda_fp16.h>
#include <cstdint>

// ---------------------------------------------------------------------------
// MetaCNNLSTM: conv1d(64->256,k9,same) + GN(8)+ReLU -> 3x LSTM(512) -> mean -> head(50)
// B=32, T=512.
// LSTM: 4 independent groups of 8 batches; 32 persistent blocks/group (16 cells),
// compensated fp16 HMMA (3 passes), W-hi fragments in registers (R10-proven).
// NEW vs best: RED-based barrier arrivals (27cyc vs ~1.2k), h exchange via
// ld.cg+STS (no TMA on critical path), direct u16 publish + double-buffered h.
// ---------------------------------------------------------------------------

#define B_      32
#define CIN     64
#define T_      512
#define NF      256
#define GN_G    8
#define KW      9
#define H_      512
#define G4H     2048
#define NCLS    50

#define NBLK    128            // 4 groups x 32 blocks
#define GRP     32
#define THR     256

// lstm dynamic smem layout (byte offsets from 1024-aligned base)
#define SM_WHI   0          // W hi: 64 rows x 64 chunks(16B) fp16, chunk^=(row&7)  65536
#define SM_WLO   65536      // W lo                                                 65536
#define SM_BH    131072     // h: [img(2)][b(8)][1024B]                             16384
#define SM_GSM   147456     // gates 2(k-half) x [64][10] fp32                       5120
#define SM_XGS   152576     // xg staging 2 x [8][64] fp32                           4096
#define SM_MBAR  156672     // mbarrier (xg prefetch only)
#define SM_TOTAL 156680
#define SMEM_REQ (SM_TOTAL + 1024)

// xg HMMA kernel smem layout
#define XGS_AHI  0
#define XGS_ALO  32768
#define XGS_BHI  65536
#define XGS_BLO  98304
#define XG_SMEM_TOTAL 131072
#define XG_SMEM_REQ (XG_SMEM_TOTAL + 1024)

// ---- global scratch ----
__device__ float g_conv[B_ * NF * T_];
__device__ float g_bufA[B_ * T_ * H_];
__device__ float g_bufB[B_ * T_ * H_];
// [t][blk(128)][b_local(8)][gate*16+cl]  -- 2KB per (t, blk)
__device__ __align__(4096) float g_xg[T_ * NBLK * 8 * 64];
// h: [buf(2)][group(4)][img(2)][b(8)][1024B] = 2 x 64KB (double-buffered)
__device__ __align__(1024) __half g_h2[2 * 4 * 2 * 8 * 512];
// barrier counters/gens padded 128B apart per group
__device__ unsigned g_cnt[4 * 32];
__device__ unsigned g_gen2[4 * 32];

// ---------------------------------------------------------------------------
// helpers
// ---------------------------------------------------------------------------
__device__ __forceinline__ float sigmoidf(float x) { return 1.0f / (1.0f + __expf(-x)); }
__device__ __forceinline__ float tanh_fast(float x) { return 1.0f - 2.0f / (1.0f + __expf(2.0f * x)); }

__device__ __forceinline__ unsigned ld_acquire(unsigned* p) {
    unsigned v;
    asm volatile("ld.acquire.gpu.global.u32 %0, [%1];" : "=r"(v) : "l"(p) : "memory");
    return v;
}
__device__ __forceinline__ void st_release(unsigned* p, unsigned v) {
    asm volatile("st.release.gpu.global.u32 [%0], %1;" :: "l"(p), "r"(v) : "memory");
}
__device__ __forceinline__ void red_add_release(unsigned* p, unsigned v) {
    asm volatile("red.release.gpu.global.add.u32 [%0], %1;" :: "l"(p), "r"(v) : "memory");
}
__device__ __forceinline__ uint32_t smem_u32(const void* p) {
    uint32_t a;
    asm("{ .reg .u64 t; cvta.to.shared.u64 t, %1; cvt.u32.u64 %0, t; }" : "=r"(a) : "l"(p));
    return a;
}
__device__ __forceinline__ uint4 ldg_cg_v4(const void* p) {
    uint4 v;
    asm volatile("ld.global.cg.v4.u32 {%0,%1,%2,%3}, [%4];"
                 : "=r"(v.x), "=r"(v.y), "=r"(v.z), "=r"(v.w) : "l"(p));
    return v;
}
__device__ __forceinline__ uint32_t split_pair_h(float a, float b, uint32_t& lo_out) {
    __half ha = __float2half_rn(a), hb = __float2half_rn(b);
    float la = a - __half2float(ha);
    float lb = b - __half2float(hb);
    __half2 lo2 = __halves2half2(__float2half_rn(la), __float2half_rn(lb));
    __half2 hi2 = __halves2half2(ha, hb);
    lo_out = *reinterpret_cast<uint32_t*>(&lo2);
    return *reinterpret_cast<uint32_t*>(&hi2);
}
__device__ __forceinline__ void sts128(uint32_t addr, uint4 v) {
    asm volatile("st.shared.v4.b32 [%0], {%1,%2,%3,%4};"
                 :: "r"(addr), "r"(v.x), "r"(v.y), "r"(v.z), "r"(v.w) : "memory");
}
__device__ __forceinline__ void ldmatrix4(uint32_t& r0, uint32_t& r1, uint32_t& r2, uint32_t& r3, uint32_t addr) {
    asm volatile("ldmatrix.sync.aligned.m8n8.x4.shared.b16 {%0,%1,%2,%3}, [%4];"
                 : "=r"(r0), "=r"(r1), "=r"(r2), "=r"(r3) : "r"(addr));
}
__device__ __forceinline__ void ldmatrix2(uint32_t& r0, uint32_t& r1, uint32_t addr) {
    asm volatile("ldmatrix.sync.aligned.m8n8.x2.shared.b16 {%0,%1}, [%2];"
                 : "=r"(r0), "=r"(r1) : "r"(addr));
}
__device__ __forceinline__ void mma16816h(float* c, const uint32_t* a, uint32_t b0, uint32_t b1) {
    asm volatile("mma.sync.aligned.m16n8k16.row.col.f32.f16.f16.f32 "
                 "{%0,%1,%2,%3}, {%4,%5,%6,%7}, {%8,%9}, {%0,%1,%2,%3};"
                 : "+f"(c[0]), "+f"(c[1]), "+f"(c[2]), "+f"(c[3])
                 : "r"(a[0]), "r"(a[1]), "r"(a[2]), "r"(a[3]), "r"(b0), "r"(b1));
}

#define MBAR_WAIT(mbar, ph) do {                                                   \
    uint32_t _done;                                                                \
    asm volatile("{\n\t.reg .pred p;\n\t"                                          \
        "mbarrier.try_wait.parity.acquire.cta.shared::cta.b64 p, [%1], %2;\n\t"    \
        "selp.b32 %0, 1, 0, p;\n\t}"                                               \
        : "=r"(_done) : "r"(mbar), "r"(ph) : "memory");                            \
    if (!_done) {                                                                  \
        asm volatile("{\n\t.reg .pred P1;\n\t"                                     \
            "WL_%=:\n\t"                                                           \
            "mbarrier.try_wait.parity.acquire.cta.shared::cta.b64 P1, [%0], %1, 0x989680;\n\t" \
            "@P1 bra.uni WD_%=;\n\t"                                               \
            "bra.uni WL_%=;\n\t"                                                   \
            "WD_%=:\n\t}"                                                          \
            :: "r"(mbar), "r"(ph) : "memory");                                     \
    }                                                                              \
} while (0)

// ---------------------------------------------------------------------------
// conv1d
// ---------------------------------------------------------------------------
__global__ void conv_kernel(const float* __restrict__ x, const float* __restrict__ w) {
    int bf = blockIdx.x;
    int b = bf >> 8, f = bf & 255;
    __shared__ float wsh[CIN * KW];
    for (int e = threadIdx.x; e < CIN * KW; e += blockDim.x)
        wsh[e] = w[f * CIN * KW + e];
    __syncthreads();
    const float* xb = x + b * CIN * T_;
    #pragma unroll
    for (int tt = 0; tt < 4; ++tt) {
        int t = tt * 128 + threadIdx.x;
        float acc = 0.f;
        for (int c = 0; c < CIN; ++c) {
            const float* xr = xb + c * T_;
            const float* wr = wsh + c * KW;
            #pragma unroll
            for (int k = 0; k < KW; ++k) {
                int ti = t + k - 4;
                if (ti >= 0 && ti < T_) acc += xr[ti] * wr[k];
            }
        }
        g_conv[(b * NF + f) * T_ + t] = acc;
    }
}

// ---------------------------------------------------------------------------
// fused GroupNorm (stats + apply + ReLU + transpose -> g_bufA)
// ---------------------------------------------------------------------------
__global__ void gn_kernel(const float* __restrict__ gamma, const float* __restrict__ beta) {
    int bg = blockIdx.x;
    int b = bg >> 3, g = bg & 7;
    const float* base = g_conv + (b * NF + g * 32) * T_;
    float s = 0.f, ss = 0.f;
    for (int e = threadIdx.x; e < 32 * T_; e += blockDim.x) {
        float v = base[e];
        s += v; ss += v * v;
    }
    __shared__ float sh_s[256], sh_q[256];
    sh_s[threadIdx.x] = s; sh_q[threadIdx.x] = ss;
    __syncthreads();
    for (int st = 128; st > 0; st >>= 1) {
        if (threadIdx.x < st) {
            sh_s[threadIdx.x] += sh_s[threadIdx.x + st];
            sh_q[threadIdx.x] += sh_q[threadIdx.x + st];
        }
        __syncthreads();
    }
    __shared__ float sh_mu, sh_rs;
    if (threadIdx.x == 0) {
        float n = 32.0f * (float)T_;
        float mu = sh_s[0] / n;
        float var = sh_q[0] / n - mu * mu;
        sh_mu = mu;
        sh_rs = rsqrtf(var + 1e-5f);
    }
    __syncthreads();
    float mu = sh_mu, rs = sh_rs;
    for (int e = threadIdx.x; e < 32 * T_; e += blockDim.x) {
        int cl = e >> 9, t = e & 511;
        int f = g * 32 + cl;
        float v = (base[e] - mu) * rs * gamma[f] + beta[f];
        v = fmaxf(v, 0.f);
        g_bufA[(b * T_ + t) * NF + f] = v;
    }
}

// ---------------------------------------------------------------------------
// xg projection GEMM on HMMA (compensated fp16, 3 passes).
// output: g_xg[((t*128 + blk)*8 + b_local)*64 + gate*16 + cl]
//   blk = (b>>3)*32 + (cell>>4), b_local = b&7, cl = cell&15
// ---------------------------------------------------------------------------
__global__ __launch_bounds__(256) void xg_hmma_kernel(int layer,
                                                      const float* __restrict__ Wih,
                                                      const float* __restrict__ bias,
                                                      int Din) {
    const float* X = (layer == 2) ? g_bufB : g_bufA;
    extern __shared__ char smraw[];
    uint32_t rawa = smem_u32(smraw);
    uint32_t base = (rawa + 1023u) & ~1023u;
    uint32_t aHI = base + XGS_AHI;
    uint32_t aLO = base + XGS_ALO;
    uint32_t bHI = base + XGS_BHI;
    uint32_t bLO = base + XGS_BLO;

    const int tid = threadIdx.x;
    const int wid = tid >> 5, lane = tid & 31;
    const int n0 = blockIdx.x * 128, m0 = blockIdx.y * 128;

    const int wm = wid & 1, wn = wid >> 1;
    const int lrow = lane & 15, lk = lane >> 4;
    const int bcs = (lane >> 3) & 1;

    const int r = tid & 127, hf = tid >> 7;
    const int mg = m0 + r;
    const float* asrc0 = X + ((size_t)(mg & 31) * T_ + (mg >> 5)) * Din + hf * 64;
    const float* bsrc0 = Wih + (size_t)(n0 + r) * Din + hf * 64;
    const uint32_t stoff0 = (uint32_t)(r * 256);

    float acc[4][4][4];
    #pragma unroll
    for (int mi = 0; mi < 4; ++mi)
        #pragma unroll
        for (int ni = 0; ni < 4; ++ni)
            #pragma unroll
            for (int q = 0; q < 4; ++q) acc[mi][ni][q] = 0.f;

    const int nchunks = Din >> 7;
    for (int kc = 0; kc < nchunks; ++kc) {
        const float* asrc = asrc0 + kc * 128;
        const float* bsrc = bsrc0 + kc * 128;
        #pragma unroll
        for (int j = 0; j < 8; ++j) {
            int c = hf * 8 + j;
            uint32_t off = stoff0 + (uint32_t)(((c ^ (r & 7))) << 4);
            {
                float4 f0 = *(const float4*)(asrc + j * 8);
                float4 f1 = *(const float4*)(asrc + j * 8 + 4);
                uint4 vh, vl;
                vh.x = split_pair_h(f0.x, f0.y, vl.x);
                vh.y = split_pair_h(f0.z, f0.w, vl.y);
                vh.z = split_pair_h(f1.x, f1.y, vl.z);
                vh.w = split_pair_h(f1.z, f1.w, vl.w);
                sts128(aHI + off, vh);
                sts128(aLO + off, vl);
            }
            {
                float4 f0 = *(const float4*)(bsrc + j * 8);
                float4 f1 = *(const float4*)(bsrc + j * 8 + 4);
                uint4 vh, vl;
                vh.x = split_pair_h(f0.x, f0.y, vl.x);
                vh.y = split_pair_h(f0.z, f0.w, vl.y);
                vh.z = split_pair_h(f1.x, f1.y, vl.z);
                vh.w = split_pair_h(f1.z, f1.w, vl.w);
                sts128(bHI + off, vh);
                sts128(bLO + off, vl);
            }
        }
        __syncthreads();

        #pragma unroll
        for (int s = 0; s < 8; ++s) {
            uint32_t ahf[4][4], alf[4][4], bhf[4][2], blf[4][2];
            #pragma unroll
            for (int mi = 0; mi < 4; ++mi) {
                int rowA = wm * 64 + mi * 16 + lrow;
                uint32_t aoff = (uint32_t)(rowA * 256 + (((2 * s + lk) ^ (rowA & 7)) << 4));
                ldmatrix4(ahf[mi][0], ahf[mi][1], ahf[mi][2], ahf[mi][3], aHI + aoff);
                ldmatrix4(alf[mi][0], alf[mi][1], alf[mi][2], alf[mi][3], aLO + aoff);
            }
            #pragma unroll
            for (int ni = 0; ni < 4; ++ni) {
                int rowB = wn * 32 + ni * 8 + (lane & 7);
                uint32_t boff = (uint32_t)(rowB * 256 + (((2 * s + bcs) ^ (rowB & 7)) << 4));
                ldmatrix2(bhf[ni][0], bhf[ni][1], bHI + boff);
                ldmatrix2(blf[ni][0], blf[ni][1], bLO + boff);
            }
            #pragma unroll
            for (int mi = 0; mi < 4; ++mi)
                #pragma unroll
                for (int ni = 0; ni < 4; ++ni) {
                    mma16816h(acc[mi][ni], ahf[mi], bhf[ni][0], bhf[ni][1]);
                    mma16816h(acc[mi][ni], ahf[mi], blf[ni][0], blf[ni][1]);
                    mma16816h(acc[mi][ni], alf[mi], bhf[ni][0], bhf[ni][1]);
                }
        }
        __syncthreads();
    }

    #pragma unroll
    for (int mi = 0; mi < 4; ++mi) {
        #pragma unroll
        for (int ni = 0; ni < 4; ++ni) {
            int cb = n0 + wn * 32 + ni * 8 + (lane & 3) * 2;
            int gate = cb >> 9, cell = cb & 511;
            int cblk = cell >> 4, cl = cell & 15;
            float bz0 = bias[cb], bz1 = bias[cb + 1];
            #pragma unroll
            for (int hrow = 0; hrow < 2; ++hrow) {
                int row = m0 + wm * 64 + mi * 16 + (lane >> 2) + hrow * 8;
                int t = row >> 5, b = row & 31;
                int blk = (b >> 3) * 32 + cblk;
                float2 v = make_float2(acc[mi][ni][hrow * 2 + 0] + bz0,
                                       acc[mi][ni][hrow * 2 + 1] + bz1);
                *(float2*)&g_xg[(((size_t)t * NBLK + blk) * 8 + (b & 7)) * 64 + gate * 16 + cl] = v;
            }
        }
    }
}

// ---------------------------------------------------------------------------
// persistent HMMA LSTM: 4 groups x 32 blocks. Block bx: group g=bx>>5 (batches
// g*8..+8), cells (bx&31)*16..+16. 8 warps = 4(m16) x 2(k-half).
// RED-arrival barrier, h via ld.cg+STS (double-buffered), direct u16 publish.
// ---------------------------------------------------------------------------
__global__ __launch_bounds__(THR, 1) void lstm_kernel(const float* __restrict__ Whh,
                                                      const float* __restrict__ xg,
                                                      float* __restrict__ Y) {
    extern __shared__ char smraw[];
    uint32_t rawa = smem_u32(smraw);
    uint32_t base = (rawa + 1023u) & ~1023u;
    char* sbase = smraw + (base - rawa);
    uint32_t wHI  = base + SM_WHI;
    uint32_t wLO  = base + SM_WLO;
    uint32_t bBH  = base + SM_BH;
    float*   gsm  = (float*)(sbase + SM_GSM);
    float*   xgs  = (float*)(sbase + SM_XGS);
    uint32_t mbar = base + SM_MBAR;
    uint32_t xgs_a = base + SM_XGS;

    const int tid = threadIdx.x;
    const int bx = blockIdx.x;
    const int g  = bx >> 5;            // batch group (0..3)
    const int ci = bx & 31;            // cell-block index (0..31)
    const int c0 = ci * 16;
    const int wid = tid >> 5, lane = tid & 31;

    unsigned* cntp = &g_cnt[g * 32];
    unsigned* genp = &g_gen2[g * 32];
    unsigned mygen = *((volatile unsigned*)genp);

    if (tid == 0) {
        asm volatile("mbarrier.init.shared.b64 [%0], %1;" :: "r"(mbar), "r"(1u) : "memory");
    }

    // --- stage W tile: 64 rows x 64 chunks(16B), fp32 -> fp16 hi/lo, chunk^=(row&7) ---
    #pragma unroll
    for (int i = 0; i < 16; ++i) {
        int gg = tid + i * 256;           // 4096 chunks
        int r = gg >> 6, k16 = gg & 63;
        int j = (r & 3) * 512 + c0 + (r >> 2);
        const float* src = Whh + (size_t)j * 512 + k16 * 8;
        float4 f0 = *(const float4*)(src);
        float4 f1 = *(const float4*)(src + 4);
        uint4 vh, vl;
        vh.x = split_pair_h(f0.x, f0.y, vl.x);
        vh.y = split_pair_h(f0.z, f0.w, vl.y);
        vh.z = split_pair_h(f1.x, f1.y, vl.z);
        vh.w = split_pair_h(f1.z, f1.w, vl.w);
        uint32_t off = (uint32_t)((r << 10) + (((k16 ^ (r & 7))) << 4));
        sts128(wHI + off, vh);
        sts128(wLO + off, vl);
    }

    // --- zero this block's chunks (2ci, 2ci+1) of both images in h-buffer 0 ---
    if (tid < 32) {
        int q = tid & 1, b = (tid >> 1) & 7, img = tid >> 4;
        uint32_t off = (uint32_t)(g * 16384 + img * 8192 + b * 1024 + (((2 * ci + q) ^ (b & 7)) << 4));
        *(uint4*)((char*)g_h2 + off) = make_uint4(0, 0, 0, 0);
    }
    __syncthreads();

    // GEMM thread mapping: 4m x 2k
    const int wm = wid & 3, wk = wid >> 2;
    const int lrow = lane & 15, lk = lane >> 4;
    const uint32_t arowoff = (uint32_t)(((wm * 16 + lrow) << 10));
    const int ax7 = lrow & 7;

    // --- hoist W-hi fragments (this warp's k-half) into registers ---
    uint32_t AH[16][4];
    #pragma unroll
    for (int ks = 0; ks < 16; ++ks) {
        int ch = (wk * 16 + ks) * 2 + lk;
        uint32_t aoff = (uint32_t)(((ch ^ ax7)) << 4);
        ldmatrix4(AH[ks][0], AH[ks][1], AH[ks][2], AH[ks][3], wHI + arowoff + aoff);
    }

    // --- prologue: prefetch xg(0) into slot 0 + initial barrier ---
    if (tid == 0) {
        asm volatile("mbarrier.arrive.expect_tx.shared.b64 _, [%0], %1;"
                     :: "r"(mbar), "r"(2048u) : "memory");
        asm volatile("cp.async.bulk.shared::cluster.global.mbarrier::complete_tx::bytes "
                     "[%0], [%1], %2, [%3];"
                     :: "r"(xgs_a), "l"((const char*)(xg + (size_t)bx * 512)), "r"(2048u), "r"(mbar) : "memory");
        __threadfence();
        red_add_release(cntp, 1u);
        if (ci == 0) {
            while (ld_acquire(cntp) < (unsigned)GRP) {}
            *((volatile unsigned*)cntp) = 0u;
            st_release(genp, mygen + 1u);
        } else {
            while (ld_acquire(genp) == mygen) {}
        }
    }
    mygen++;
    __syncthreads();

    // B-frag addressing (8 batch rows, 1024B row stride; hi at +0, lo at +8192)
    const int brow = lane & 7;
    const uint32_t browoff = (uint32_t)(brow << 10);
    const int bx7 = brow;
    const int bcs = (lane >> 3) & 1;

    // activation mapping: cl = tid>>3 (0..15), b_local = tid&7  (tid < 128)
    const int cl = tid >> 3;
    const int bb = tid & 7;
    float cst = 0.f;
    const uint32_t pub_base = (uint32_t)(g * 16384 + bb * 1024
                                         + (((2 * ci + (cl >> 3)) ^ (bb & 7)) << 4) + (cl & 7) * 2);

    for (int t = 0; t < T_; ++t) {
        // 1. gather h(t-1) from buffer t&1 via ld.cg (64B/thread) into regs
        const char* hs = (const char*)g_h2 + (size_t)(t & 1) * 65536 + g * 16384;
        uint4 hv0 = ldg_cg_v4(hs + tid * 16);
        uint4 hv1 = ldg_cg_v4(hs + tid * 16 + 4096);
        uint4 hv2 = ldg_cg_v4(hs + tid * 16 + 8192);
        uint4 hv3 = ldg_cg_v4(hs + tid * 16 + 12288);

        // tid0: ensure xg(t) landed, then prefetch xg(t+1) into slot (t+1)&1
        if (tid == 0) {
            MBAR_WAIT(mbar, (uint32_t)(t & 1));
            if (t + 1 < T_) {
                const char* xsrc = (const char*)(xg + (((size_t)(t + 1) * NBLK + bx) * 512));
                asm volatile("mbarrier.arrive.expect_tx.shared.b64 _, [%0], %1;"
                             :: "r"(mbar), "r"(2048u) : "memory");
                asm volatile("cp.async.bulk.shared::cluster.global.mbarrier::complete_tx::bytes "
                             "[%0], [%1], %2, [%3];"
                             :: "r"(xgs_a + (((t + 1) & 1) ? 2048u : 0u)), "l"(xsrc), "r"(2048u), "r"(mbar) : "memory");
            }
        }

        // 2. stage h into smem (same offsets) and sync
        sts128(bBH + tid * 16, hv0);
        sts128(bBH + tid * 16 + 4096, hv1);
        sts128(bBH + tid * 16 + 8192, hv2);
        sts128(bBH + tid * 16 + 12288, hv3);
        __syncthreads();

        // 3. GEMM: 16 k-steps (this warp's half), 3 accumulator chains
        float acc_a[4] = {0.f, 0.f, 0.f, 0.f};
        float acc_b[4] = {0.f, 0.f, 0.f, 0.f};
        float acc_c[4] = {0.f, 0.f, 0.f, 0.f};
        #pragma unroll
        for (int ks = 0; ks < 16; ++ks) {
            int chA = (wk * 16 + ks) * 2 + lk;
            int chB = (wk * 16 + ks) * 2 + bcs;
            uint32_t aoff = (uint32_t)(((chA ^ ax7)) << 4);
            uint32_t boff = (uint32_t)(((chB ^ bx7)) << 4);
            uint32_t al0, al1, al2, al3;
            uint32_t bh0, bh1, bl0, bl1;
            ldmatrix4(al0, al1, al2, al3, wLO + arowoff + aoff);
            ldmatrix2(bh0, bh1, bBH + browoff + boff);
            ldmatrix2(bl0, bl1, (bBH + 8192u) + browoff + boff);
            mma16816h(acc_a, AH[ks], bh0, bh1);
            mma16816h(acc_b, AH[ks], bl0, bl1);
            uint32_t alr[4] = {al0, al1, al2, al3};
            mma16816h(acc_c, alr, bh0, bh1);
        }

        // 4. combine + store per-k-half gates to gsm[wk] ([64][10])
        {
            int r0 = wm * 16 + (lane >> 2);
            int cb = (lane & 3) * 2;
            float* gk = gsm + wk * 640;
            float s0 = acc_a[0] + acc_b[0] + acc_c[0];
            float s1 = acc_a[1] + acc_b[1] + acc_c[1];
            float s2 = acc_a[2] + acc_b[2] + acc_c[2];
            float s3 = acc_a[3] + acc_b[3] + acc_c[3];
            *(float2*)&gk[r0 * 10 + cb]       = make_float2(s0, s1);
            *(float2*)&gk[(r0 + 8) * 10 + cb] = make_float2(s2, s3);
        }
        __syncthreads();

        // 5. activation + DIRECT publish into h-buffer (t+1)&1
        if (tid < 128) {
            const float* xb2 = xgs + ((t & 1) ? 512 : 0) + bb * 64;
            int r = cl * 4;
            float gi = gsm[(r + 0) * 10 + bb] + gsm[640 + (r + 0) * 10 + bb] + xb2[cl];
            float gf = gsm[(r + 1) * 10 + bb] + gsm[640 + (r + 1) * 10 + bb] + xb2[16 + cl];
            float gg = gsm[(r + 2) * 10 + bb] + gsm[640 + (r + 2) * 10 + bb] + xb2[32 + cl];
            float go = gsm[(r + 3) * 10 + bb] + gsm[640 + (r + 3) * 10 + bb] + xb2[48 + cl];
            float iv = sigmoidf(gi);
            float fv = sigmoidf(gf);
            float gv = tanh_fast(gg);
            float ov = sigmoidf(go);
            cst = fv * cst + iv * gv;
            float hv = ov * tanh_fast(cst);
            __half hh = __float2half_rn(hv);
            __half hl = __float2half_rn(hv - __half2float(hh));
            char* pb = (char*)g_h2 + (size_t)((t + 1) & 1) * 65536 + pub_base;
            *(__half*)pb = hh;
            *(__half*)(pb + 8192) = hl;
            Y[((size_t)(g * 8 + bb) * T_ + t) * H_ + c0 + cl] = hv;
        }

        // 6. barrier: RED arrival + single releaser per group
        __syncthreads();
        if (tid == 0) {
            __threadfence();
            red_add_release(cntp, 1u);
            if (ci == 0) {
                while (ld_acquire(cntp) < (unsigned)GRP) {}
                *((volatile unsigned*)cntp) = 0u;
                st_release(genp, mygen + 1u);
            } else {
                while (ld_acquire(genp) == mygen) {}
            }
        }
        mygen++;
        __syncthreads();
    }
}

// ---------------------------------------------------------------------------
// mean over T + head GEMV
// ---------------------------------------------------------------------------
__global__ void pool_head_kernel(const float* __restrict__ head_w,
                                 const float* __restrict__ head_b,
                                 float* __restrict__ out) {
    int b = blockIdx.x;
    int h = threadIdx.x;
    __shared__ float feat[H_];
    const float* Yp = g_bufB + (size_t)b * T_ * H_;
    float s = 0.f;
    for (int t = 0; t < T_; ++t) s += Yp[t * H_ + h];
    feat[h] = s * (1.0f / (float)T_);
    __syncthreads();
    for (int cc = threadIdx.x; cc < NCLS; cc += blockDim.x) {
        float a = head_b[cc];
        const float* wr = head_w + cc * H_;
        for (int k = 0; k < H_; ++k) a += feat[k] * wr[k];
        out[b * NCLS + cc] = a;
    }
}

// ---------------------------------------------------------------------------
extern "C" void kernel_launch(void* const* d_in, const int* in_sizes, int n_in,
                              void* d_out, int out_size) {
    const float* x     = (const float*)d_in[0];
    const float* convw = (const float*)d_in[1];
    const float* gamma = (const float*)d_in[2];
    const float* beta  = (const float*)d_in[3];

    bool head_first = (in_sizes[4] == NCLS * H_);
    int o = head_first ? 6 : 4;
    const float* headw = (const float*)d_in[head_first ? 4 : 13];
    const float* headb = (const float*)d_in[head_first ? 5 : 14];
    const float* wih[3] = { (const float*)d_in[o + 0], (const float*)d_in[o + 3], (const float*)d_in[o + 6] };
    const float* whh[3] = { (const float*)d_in[o + 1], (const float*)d_in[o + 4], (const float*)d_in[o + 7] };
    const float* bb[3]  = { (const float*)d_in[o + 2], (const float*)d_in[o + 5], (const float*)d_in[o + 8] };

    static int smem_set = 0;
    if (!smem_set) {
        cudaFuncSetAttribute(lstm_kernel, cudaFuncAttributeMaxDynamicSharedMemorySize, SMEM_REQ);
        cudaFuncSetAttribute(xg_hmma_kernel, cudaFuncAttributeMaxDynamicSharedMemorySize, XG_SMEM_REQ);
        smem_set = 1;
    }

    void* xgsym = nullptr;   cudaGetSymbolAddress(&xgsym, g_xg);
    void* bufAsym = nullptr; cudaGetSymbolAddress(&bufAsym, g_bufA);
    void* bufBsym = nullptr; cudaGetSymbolAddress(&bufBsym, g_bufB);

    conv_kernel<<<B_ * NF, 128>>>(x, convw);
    gn_kernel<<<B_ * GN_G, 256>>>(gamma, beta);

    for (int layer = 1; layer <= 3; ++layer) {
        int din = (layer == 1) ? NF : H_;
        dim3 gg(G4H / 128, (B_ * T_) / 128);
        xg_hmma_kernel<<<gg, 256, XG_SMEM_REQ>>>(layer, wih[layer - 1], bb[layer - 1], din);
        float* yptr = (layer == 2) ? (float*)bufAsym : (float*)bufBsym;
        lstm_kernel<<<NBLK, THR, SMEM_REQ>>>(whh[layer - 1], (const float*)xgsym, yptr);
    }

    pool_head_kernel<<<B_, H_>>>(headw, headb, (float*)d_out);
}

// round 14
// speedup vs baseline: 1.0748x; 1.0477x over previous
#include <cuda_runtime.h>
#include <cuda_bf16.h>
#include <cuda_fp16.h>
#include <cstdint>

// ---------------------------------------------------------------------------
// MetaCNNLSTM: conv1d(64->256,k9,same) + GN(8)+ReLU -> 3x LSTM(512) -> mean -> head(50)
// B=32, T=512.
// LSTM: 4 independent groups of 8 batches; 32 persistent blocks/group (16 cells),
// compensated fp16 HMMA (3 passes), W-hi fragments in registers, flat atomic
// barrier (R11-proven, 7439us base).
// NEW: MUFU-minimized activation (clamped ex2 + batched rcp.approx):
//   10 MUFU + IEEE-div fixups per (cell,batch) -> 7 MUFU, no fixup chains.
// ---------------------------------------------------------------------------

#define B_      32
#define CIN     64
#define T_      512
#define NF      256
#define GN_G    8
#define KW      9
#define H_      512
#define G4H     2048
#define NCLS    50

#define NBLK    128            // 4 groups x 32 blocks
#define GRP     32
#define THR     256

// lstm dynamic smem layout (byte offsets from 1024-aligned base)
#define SM_WHI   0          // W hi: 64 rows x 64 chunks(16B) fp16, chunk^=(row&7)  65536
#define SM_WLO   65536      // W lo                                                 65536
#define SM_BHI   131072     // h hi: 8 rows x 64 chunks                              8192
#define SM_BLO   139264     // h lo (contiguous: one bulk copy)                      8192
#define SM_GSM   147456     // gates 2(k-half) x [64][10] fp32                       5120
#define SM_XGS   152576     // xg staging 2 x [8][64] fp32                           4096
#define SM_HSMH  156672     // h hi staging [8][16] fp16                              256
#define SM_HSML  156928     // h lo staging                                           256
#define SM_MBAR  157184     // mbarrier (8B)
#define SM_TOTAL 157192
#define SMEM_REQ (SM_TOTAL + 1024)

// xg HMMA kernel smem layout
#define XGS_AHI  0
#define XGS_ALO  32768
#define XGS_BHI  65536
#define XGS_BLO  98304
#define XG_SMEM_TOTAL 131072
#define XG_SMEM_REQ (XG_SMEM_TOTAL + 1024)

// ---- global scratch ----
__device__ float g_conv[B_ * NF * T_];
__device__ float g_bufA[B_ * T_ * H_];
__device__ float g_bufB[B_ * T_ * H_];
// [t][blk(128)][b_local(8)][gate*16+cl]  -- 2KB per (t, blk)
__device__ __align__(4096) float g_xg[T_ * NBLK * 8 * 64];
// h: [group(4)][img(2)][b_local(8) rows of 1024B, chunk k16^(b&7)] = 4 x 16KB
__device__ __align__(1024) __half g_h2[4 * 2 * 8 * H_];
// barrier counters/gens padded 128B apart (4 groups)
__device__ unsigned g_barc[4 * 32];
__device__ unsigned g_gen2[4 * 32];

// ---------------------------------------------------------------------------
// helpers
// ---------------------------------------------------------------------------
__device__ __forceinline__ unsigned ld_acquire(unsigned* p) {
    unsigned v;
    asm volatile("ld.acquire.gpu.global.u32 %0, [%1];" : "=r"(v) : "l"(p) : "memory");
    return v;
}
__device__ __forceinline__ void st_release(unsigned* p, unsigned v) {
    asm volatile("st.release.gpu.global.u32 [%0], %1;" :: "l"(p), "r"(v) : "memory");
}
__device__ __forceinline__ uint32_t smem_u32(const void* p) {
    uint32_t a;
    asm("{ .reg .u64 t; cvta.to.shared.u64 t, %1; cvt.u32.u64 %0, t; }" : "=r"(a) : "l"(p));
    return a;
}
__device__ __forceinline__ float rcp_fast(float x) {
    float r;
    asm("rcp.approx.f32 %0, %1;" : "=f"(r) : "f"(x));
    return r;
}
__device__ __forceinline__ uint32_t split_pair_h(float a, float b, uint32_t& lo_out) {
    __half ha = __float2half_rn(a), hb = __float2half_rn(b);
    float la = a - __half2float(ha);
    float lb = b - __half2float(hb);
    __half2 lo2 = __halves2half2(__float2half_rn(la), __float2half_rn(lb));
    __half2 hi2 = __halves2half2(ha, hb);
    lo_out = *reinterpret_cast<uint32_t*>(&lo2);
    return *reinterpret_cast<uint32_t*>(&hi2);
}
__device__ __forceinline__ void sts128(uint32_t addr, uint4 v) {
    asm volatile("st.shared.v4.b32 [%0], {%1,%2,%3,%4};"
                 :: "r"(addr), "r"(v.x), "r"(v.y), "r"(v.z), "r"(v.w) : "memory");
}
__device__ __forceinline__ void ldmatrix4(uint32_t& r0, uint32_t& r1, uint32_t& r2, uint32_t& r3, uint32_t addr) {
    asm volatile("ldmatrix.sync.aligned.m8n8.x4.shared.b16 {%0,%1,%2,%3}, [%4];"
                 : "=r"(r0), "=r"(r1), "=r"(r2), "=r"(r3) : "r"(addr));
}
__device__ __forceinline__ void ldmatrix2(uint32_t& r0, uint32_t& r1, uint32_t addr) {
    asm volatile("ldmatrix.sync.aligned.m8n8.x2.shared.b16 {%0,%1}, [%2];"
                 : "=r"(r0), "=r"(r1) : "r"(addr));
}
__device__ __forceinline__ void mma16816h(float* c, const uint32_t* a, uint32_t b0, uint32_t b1) {
    asm volatile("mma.sync.aligned.m16n8k16.row.col.f32.f16.f16.f32 "
                 "{%0,%1,%2,%3}, {%4,%5,%6,%7}, {%8,%9}, {%0,%1,%2,%3};"
                 : "+f"(c[0]), "+f"(c[1]), "+f"(c[2]), "+f"(c[3])
                 : "r"(a[0]), "r"(a[1]), "r"(a[2]), "r"(a[3]), "r"(b0), "r"(b1));
}

#define MBAR_WAIT(mbar, ph) do {                                                   \
    uint32_t _done;                                                                \
    asm volatile("{\n\t.reg .pred p;\n\t"                                          \
        "mbarrier.try_wait.parity.acquire.cta.shared::cta.b64 p, [%1], %2;\n\t"    \
        "selp.b32 %0, 1, 0, p;\n\t}"                                               \
        : "=r"(_done) : "r"(mbar), "r"(ph) : "memory");                            \
    if (!_done) {                                                                  \
        asm volatile("{\n\t.reg .pred P1;\n\t"                                     \
            "WL_%=:\n\t"                                                           \
            "mbarrier.try_wait.parity.acquire.cta.shared::cta.b64 P1, [%0], %1, 0x989680;\n\t" \
            "@P1 bra.uni WD_%=;\n\t"                                               \
            "bra.uni WL_%=;\n\t"                                                   \
            "WD_%=:\n\t}"                                                          \
            :: "r"(mbar), "r"(ph) : "memory");                                     \
    }                                                                              \
} while (0)

// ---------------------------------------------------------------------------
// conv1d
// ---------------------------------------------------------------------------
__global__ void conv_kernel(const float* __restrict__ x, const float* __restrict__ w) {
    int bf = blockIdx.x;
    int b = bf >> 8, f = bf & 255;
    __shared__ float wsh[CIN * KW];
    for (int e = threadIdx.x; e < CIN * KW; e += blockDim.x)
        wsh[e] = w[f * CIN * KW + e];
    __syncthreads();
    const float* xb = x + b * CIN * T_;
    #pragma unroll
    for (int tt = 0; tt < 4; ++tt) {
        int t = tt * 128 + threadIdx.x;
        float acc = 0.f;
        for (int c = 0; c < CIN; ++c) {
            const float* xr = xb + c * T_;
            const float* wr = wsh + c * KW;
            #pragma unroll
            for (int k = 0; k < KW; ++k) {
                int ti = t + k - 4;
                if (ti >= 0 && ti < T_) acc += xr[ti] * wr[k];
            }
        }
        g_conv[(b * NF + f) * T_ + t] = acc;
    }
}

// ---------------------------------------------------------------------------
// fused GroupNorm (stats + apply + ReLU + transpose -> g_bufA)
// ---------------------------------------------------------------------------
__global__ void gn_kernel(const float* __restrict__ gamma, const float* __restrict__ beta) {
    int bg = blockIdx.x;
    int b = bg >> 3, g = bg & 7;
    const float* base = g_conv + (b * NF + g * 32) * T_;
    float s = 0.f, ss = 0.f;
    for (int e = threadIdx.x; e < 32 * T_; e += blockDim.x) {
        float v = base[e];
        s += v; ss += v * v;
    }
    __shared__ float sh_s[256], sh_q[256];
    sh_s[threadIdx.x] = s; sh_q[threadIdx.x] = ss;
    __syncthreads();
    for (int st = 128; st > 0; st >>= 1) {
        if (threadIdx.x < st) {
            sh_s[threadIdx.x] += sh_s[threadIdx.x + st];
            sh_q[threadIdx.x] += sh_q[threadIdx.x + st];
        }
        __syncthreads();
    }
    __shared__ float sh_mu, sh_rs;
    if (threadIdx.x == 0) {
        float n = 32.0f * (float)T_;
        float mu = sh_s[0] / n;
        float var = sh_q[0] / n - mu * mu;
        sh_mu = mu;
        sh_rs = rsqrtf(var + 1e-5f);
    }
    __syncthreads();
    float mu = sh_mu, rs = sh_rs;
    for (int e = threadIdx.x; e < 32 * T_; e += blockDim.x) {
        int cl = e >> 9, t = e & 511;
        int f = g * 32 + cl;
        float v = (base[e] - mu) * rs * gamma[f] + beta[f];
        v = fmaxf(v, 0.f);
        g_bufA[(b * T_ + t) * NF + f] = v;
    }
}

// ---------------------------------------------------------------------------
// xg projection GEMM on HMMA (compensated fp16, 3 passes).
// output: g_xg[((t*128 + blk)*8 + b_local)*64 + gate*16 + cl]
//   blk = (b>>3)*32 + (cell>>4), b_local = b&7, cl = cell&15
// ---------------------------------------------------------------------------
__global__ __launch_bounds__(256) void xg_hmma_kernel(int layer,
                                                      const float* __restrict__ Wih,
                                                      const float* __restrict__ bias,
                                                      int Din) {
    const float* X = (layer == 2) ? g_bufB : g_bufA;
    extern __shared__ char smraw[];
    uint32_t rawa = smem_u32(smraw);
    uint32_t base = (rawa + 1023u) & ~1023u;
    uint32_t aHI = base + XGS_AHI;
    uint32_t aLO = base + XGS_ALO;
    uint32_t bHI = base + XGS_BHI;
    uint32_t bLO = base + XGS_BLO;

    const int tid = threadIdx.x;
    const int wid = tid >> 5, lane = tid & 31;
    const int n0 = blockIdx.x * 128, m0 = blockIdx.y * 128;

    const int wm = wid & 1, wn = wid >> 1;
    const int lrow = lane & 15, lk = lane >> 4;
    const int bcs = (lane >> 3) & 1;

    const int r = tid & 127, hf = tid >> 7;
    const int mg = m0 + r;
    const float* asrc0 = X + ((size_t)(mg & 31) * T_ + (mg >> 5)) * Din + hf * 64;
    const float* bsrc0 = Wih + (size_t)(n0 + r) * Din + hf * 64;
    const uint32_t stoff0 = (uint32_t)(r * 256);

    float acc[4][4][4];
    #pragma unroll
    for (int mi = 0; mi < 4; ++mi)
        #pragma unroll
        for (int ni = 0; ni < 4; ++ni)
            #pragma unroll
            for (int q = 0; q < 4; ++q) acc[mi][ni][q] = 0.f;

    const int nchunks = Din >> 7;
    for (int kc = 0; kc < nchunks; ++kc) {
        const float* asrc = asrc0 + kc * 128;
        const float* bsrc = bsrc0 + kc * 128;
        #pragma unroll
        for (int j = 0; j < 8; ++j) {
            int c = hf * 8 + j;
            uint32_t off = stoff0 + (uint32_t)(((c ^ (r & 7))) << 4);
            {
                float4 f0 = *(const float4*)(asrc + j * 8);
                float4 f1 = *(const float4*)(asrc + j * 8 + 4);
                uint4 vh, vl;
                vh.x = split_pair_h(f0.x, f0.y, vl.x);
                vh.y = split_pair_h(f0.z, f0.w, vl.y);
                vh.z = split_pair_h(f1.x, f1.y, vl.z);
                vh.w = split_pair_h(f1.z, f1.w, vl.w);
                sts128(aHI + off, vh);
                sts128(aLO + off, vl);
            }
            {
                float4 f0 = *(const float4*)(bsrc + j * 8);
                float4 f1 = *(const float4*)(bsrc + j * 8 + 4);
                uint4 vh, vl;
                vh.x = split_pair_h(f0.x, f0.y, vl.x);
                vh.y = split_pair_h(f0.z, f0.w, vl.y);
                vh.z = split_pair_h(f1.x, f1.y, vl.z);
                vh.w = split_pair_h(f1.z, f1.w, vl.w);
                sts128(bHI + off, vh);
                sts128(bLO + off, vl);
            }
        }
        __syncthreads();

        #pragma unroll
        for (int s = 0; s < 8; ++s) {
            uint32_t ahf[4][4], alf[4][4], bhf[4][2], blf[4][2];
            #pragma unroll
            for (int mi = 0; mi < 4; ++mi) {
                int rowA = wm * 64 + mi * 16 + lrow;
                uint32_t aoff = (uint32_t)(rowA * 256 + (((2 * s + lk) ^ (rowA & 7)) << 4));
                ldmatrix4(ahf[mi][0], ahf[mi][1], ahf[mi][2], ahf[mi][3], aHI + aoff);
                ldmatrix4(alf[mi][0], alf[mi][1], alf[mi][2], alf[mi][3], aLO + aoff);
            }
            #pragma unroll
            for (int ni = 0; ni < 4; ++ni) {
                int rowB = wn * 32 + ni * 8 + (lane & 7);
                uint32_t boff = (uint32_t)(rowB * 256 + (((2 * s + bcs) ^ (rowB & 7)) << 4));
                ldmatrix2(bhf[ni][0], bhf[ni][1], bHI + boff);
                ldmatrix2(blf[ni][0], blf[ni][1], bLO + boff);
            }
            #pragma unroll
            for (int mi = 0; mi < 4; ++mi)
                #pragma unroll
                for (int ni = 0; ni < 4; ++ni) {
                    mma16816h(acc[mi][ni], ahf[mi], bhf[ni][0], bhf[ni][1]);
                    mma16816h(acc[mi][ni], ahf[mi], blf[ni][0], blf[ni][1]);
                    mma16816h(acc[mi][ni], alf[mi], bhf[ni][0], bhf[ni][1]);
                }
        }
        __syncthreads();
    }

    #pragma unroll
    for (int mi = 0; mi < 4; ++mi) {
        #pragma unroll
        for (int ni = 0; ni < 4; ++ni) {
            int cb = n0 + wn * 32 + ni * 8 + (lane & 3) * 2;
            int gate = cb >> 9, cell = cb & 511;
            int cblk = cell >> 4, cl = cell & 15;
            float bz0 = bias[cb], bz1 = bias[cb + 1];
            #pragma unroll
            for (int hrow = 0; hrow < 2; ++hrow) {
                int row = m0 + wm * 64 + mi * 16 + (lane >> 2) + hrow * 8;
                int t = row >> 5, b = row & 31;
                int blk = (b >> 3) * 32 + cblk;
                float2 v = make_float2(acc[mi][ni][hrow * 2 + 0] + bz0,
                                       acc[mi][ni][hrow * 2 + 1] + bz1);
                *(float2*)&g_xg[(((size_t)t * NBLK + blk) * 8 + (b & 7)) * 64 + gate * 16 + cl] = v;
            }
        }
    }
}

// ---------------------------------------------------------------------------
// persistent HMMA LSTM: 4 groups x 32 blocks. Block bx: group g=bx>>5 (batches
// g*8..+8), cells (bx&31)*16..+16. A row r <-> (gate=r&3, cell=c0+(r>>2)).
// 8 warps = 4(m16) x 2(k-half); N=8 whole. k-halves reduced in smem.
// ---------------------------------------------------------------------------
__global__ __launch_bounds__(THR, 1) void lstm_kernel(const float* __restrict__ Whh,
                                                      const float* __restrict__ xg,
                                                      float* __restrict__ Y) {
    extern __shared__ char smraw[];
    uint32_t rawa = smem_u32(smraw);
    uint32_t base = (rawa + 1023u) & ~1023u;
    char* sbase = smraw + (base - rawa);
    uint32_t wHI  = base + SM_WHI;
    uint32_t wLO  = base + SM_WLO;
    uint32_t bHI  = base + SM_BHI;
    float*   gsm  = (float*)(sbase + SM_GSM);
    float*   xgs  = (float*)(sbase + SM_XGS);
    __half*  hsmh = (__half*)(sbase + SM_HSMH);
    __half*  hsml = (__half*)(sbase + SM_HSML);
    uint32_t mbar = base + SM_MBAR;
    uint32_t xgs_a = base + SM_XGS;

    const int tid = threadIdx.x;
    const int bx = blockIdx.x;
    const int g  = bx >> 5;            // batch group (0..3)
    const int ci = bx & 31;            // cell-block index (0..31)
    const int c0 = ci * 16;
    const int wid = tid >> 5, lane = tid & 31;

    unsigned* barc = &g_barc[g * 32];
    unsigned* genp = &g_gen2[g * 32];
    unsigned mygen = *((volatile unsigned*)genp);

    if (tid == 0) {
        asm volatile("mbarrier.init.shared.b64 [%0], %1;" :: "r"(mbar), "r"(1u) : "memory");
    }

    // --- stage W tile: 64 rows x 64 chunks(16B), fp32 -> fp16 hi/lo, chunk^=(row&7) ---
    #pragma unroll
    for (int i = 0; i < 16; ++i) {
        int gg = tid + i * 256;           // 4096 chunks
        int r = gg >> 6, k16 = gg & 63;
        int j = (r & 3) * 512 + c0 + (r >> 2);
        const float* src = Whh + (size_t)j * 512 + k16 * 8;
        float4 f0 = *(const float4*)(src);
        float4 f1 = *(const float4*)(src + 4);
        uint4 vh, vl;
        vh.x = split_pair_h(f0.x, f0.y, vl.x);
        vh.y = split_pair_h(f0.z, f0.w, vl.y);
        vh.z = split_pair_h(f1.x, f1.y, vl.z);
        vh.w = split_pair_h(f1.z, f1.w, vl.w);
        uint32_t off = (uint32_t)((r << 10) + (((k16 ^ (r & 7))) << 4));
        sts128(wHI + off, vh);
        sts128(wLO + off, vl);
    }

    // --- zero this block's chunks (2ci, 2ci+1) of both images of its group ---
    if (tid < 32) {
        int q = tid & 1, b = (tid >> 1) & 7, img = tid >> 4;
        uint32_t off = (uint32_t)(((g * 2 + img) * 8 + b) * 1024 + (((2 * ci + q) ^ (b & 7)) << 4));
        *(uint4*)((char*)g_h2 + off) = make_uint4(0, 0, 0, 0);
    }
    __syncthreads();

    // GEMM thread mapping: 4m x 2k
    const int wm = wid & 3, wk = wid >> 2;
    const int lrow = lane & 15, lk = lane >> 4;
    const uint32_t arowoff = (uint32_t)(((wm * 16 + lrow) << 10));
    const int ax7 = lrow & 7;

    // --- hoist W-hi fragments (this warp's k-half) into registers ---
    uint32_t AH[16][4];
    #pragma unroll
    for (int ks = 0; ks < 16; ++ks) {
        int ch = (wk * 16 + ks) * 2 + lk;
        uint32_t aoff = (uint32_t)(((ch ^ ax7)) << 4);
        ldmatrix4(AH[ks][0], AH[ks][1], AH[ks][2], AH[ks][3], wHI + arowoff + aoff);
    }

    // --- prologue: prefetch xg(0) + per-group initial barrier ---
    if (tid == 0) {
        asm volatile("mbarrier.arrive.expect_tx.shared.b64 _, [%0], %1;"
                     :: "r"(mbar), "r"(2048u) : "memory");
        asm volatile("cp.async.bulk.shared::cluster.global.mbarrier::complete_tx::bytes "
                     "[%0], [%1], %2, [%3];"
                     :: "r"(xgs_a), "l"((const char*)(xg + (size_t)bx * 512)), "r"(2048u), "r"(mbar) : "memory");
        __threadfence();
        unsigned a = atomicAdd(barc, 1u);
        if (a == GRP - 1u) { *barc = 0u; st_release(genp, mygen + 1u); }
        else { while (ld_acquire(genp) == mygen) {} }
    }
    mygen++;
    __syncthreads();
    MBAR_WAIT(mbar, 0u);

    // B-frag addressing (8 batch rows)
    const int brow = lane & 7;
    const uint32_t browoff = (uint32_t)(brow << 10);
    const int bx7 = brow;
    const int bcs = (lane >> 3) & 1;

    // activation mapping: cl = tid>>3 (0..15), b_local = tid&7  (tid < 128)
    const int cl = tid >> 3;
    const int bb = tid & 7;
    float cst = 0.f;

    const char* hsrc = (const char*)g_h2 + g * 16384;
    const float L2E = 1.4426950408889634f;

    for (int t = 0; t < T_; ++t) {
        // 1. bulk copies: h hi+lo (16KB) + xg(t+1) (2KB)
        if (tid == 0) {
            unsigned txb = 16384u + ((t + 1 < T_) ? 2048u : 0u);
            asm volatile("mbarrier.arrive.expect_tx.shared.b64 _, [%0], %1;"
                         :: "r"(mbar), "r"(txb) : "memory");
            asm volatile("cp.async.bulk.shared::cluster.global.mbarrier::complete_tx::bytes "
                         "[%0], [%1], %2, [%3];"
                         :: "r"(bHI), "l"(hsrc), "r"(16384u), "r"(mbar) : "memory");
            if (t + 1 < T_) {
                const char* xsrc = (const char*)(xg + (((size_t)(t + 1) * NBLK + bx) * 512));
                asm volatile("cp.async.bulk.shared::cluster.global.mbarrier::complete_tx::bytes "
                             "[%0], [%1], %2, [%3];"
                             :: "r"(xgs_a + (((t + 1) & 1) ? 2048u : 0u)), "l"(xsrc), "r"(2048u), "r"(mbar) : "memory");
            }
        }
        MBAR_WAIT(mbar, (uint32_t)((t + 1) & 1));

        // 2. GEMM: 16 k-steps (this warp's half), 3 accumulator chains
        float acc_a[4] = {0.f, 0.f, 0.f, 0.f};
        float acc_b[4] = {0.f, 0.f, 0.f, 0.f};
        float acc_c[4] = {0.f, 0.f, 0.f, 0.f};
        #pragma unroll
        for (int ks = 0; ks < 16; ++ks) {
            int chA = (wk * 16 + ks) * 2 + lk;
            int chB = (wk * 16 + ks) * 2 + bcs;
            uint32_t aoff = (uint32_t)(((chA ^ ax7)) << 4);
            uint32_t boff = (uint32_t)(((chB ^ bx7)) << 4);
            uint32_t al0, al1, al2, al3;
            uint32_t bh0, bh1, bl0, bl1;
            ldmatrix4(al0, al1, al2, al3, wLO + arowoff + aoff);
            ldmatrix2(bh0, bh1, bHI + browoff + boff);
            ldmatrix2(bl0, bl1, (bHI + 8192u) + browoff + boff);
            mma16816h(acc_a, AH[ks], bh0, bh1);
            mma16816h(acc_b, AH[ks], bl0, bl1);
            uint32_t alr[4] = {al0, al1, al2, al3};
            mma16816h(acc_c, alr, bh0, bh1);
        }

        // 3. combine + store per-k-half gates to gsm[wk] ([64][10])
        {
            int r0 = wm * 16 + (lane >> 2);
            int cb = (lane & 3) * 2;
            float* gk = gsm + wk * 640;
            float s0 = acc_a[0] + acc_b[0] + acc_c[0];
            float s1 = acc_a[1] + acc_b[1] + acc_c[1];
            float s2 = acc_a[2] + acc_b[2] + acc_c[2];
            float s3 = acc_a[3] + acc_b[3] + acc_c[3];
            *(float2*)&gk[r0 * 10 + cb]       = make_float2(s0, s1);
            *(float2*)&gk[(r0 + 8) * 10 + cb] = make_float2(s2, s3);
        }
        __syncthreads();

        // 4. activation (MUFU-minimized): 7 MUFU per (cell,batch):
        //    5 ex2 + 2 batched rcp.approx; clamps make saturation exact.
        if (tid < 128) {
            const float* xb2 = xgs + ((t & 1) ? 512 : 0) + bb * 64;
            int r = cl * 4;
            float gi = gsm[(r + 0) * 10 + bb] + gsm[640 + (r + 0) * 10 + bb] + xb2[cl];
            float gf = gsm[(r + 1) * 10 + bb] + gsm[640 + (r + 1) * 10 + bb] + xb2[16 + cl];
            float gg = gsm[(r + 2) * 10 + bb] + gsm[640 + (r + 2) * 10 + bb] + xb2[32 + cl];
            float go = gsm[(r + 3) * 10 + bb] + gsm[640 + (r + 3) * 10 + bb] + xb2[48 + cl];

            float xi = fminf(fmaxf(gi, -15.f), 15.f);
            float xf = fminf(fmaxf(gf, -15.f), 15.f);
            float xgc = fminf(fmaxf(gg, -7.5f), 7.5f);
            float ea = exp2f(-xi * L2E);           // e^{-gi}
            float eb = exp2f(-xf * L2E);           // e^{-gf}
            float eu = exp2f(xgc * (2.f * L2E));   // e^{2 gg}
            float aa = 1.f + ea, bbv = 1.f + eb, uu = 1.f + eu;
            float p2 = aa * bbv;
            float r3 = rcp_fast(p2 * uu);
            float inv_u = r3 * p2;
            float r2 = r3 * uu;                    // 1/(aa*bbv)
            float iv = r2 * bbv;                   // sigmoid(gi)
            float fv = r2 * aa;                    // sigmoid(gf)
            float gv = 1.f - 2.f * inv_u;          // tanh(gg)
            cst = fv * cst + iv * gv;

            float xo = fminf(fmaxf(go, -15.f), 15.f);
            float xc = fminf(fmaxf(cst, -7.5f), 7.5f);
            float ed = exp2f(-xo * L2E);           // e^{-go}
            float ev = exp2f(xc * (2.f * L2E));    // e^{2c}
            float dd = 1.f + ed, vv = 1.f + ev;
            float rq = rcp_fast(dd * vv);
            float inv_v = rq * dd;
            float ov = rq * vv;                    // sigmoid(go)
            float hv = ov * (1.f - 2.f * inv_v);   // sigmoid(go)*tanh(c)

            __half hh = __float2half_rn(hv);
            hsmh[bb * 16 + cl] = hh;
            hsml[bb * 16 + cl] = __float2half_rn(hv - __half2float(hh));
            Y[((size_t)(g * 8 + bb) * T_ + t) * H_ + c0 + cl] = hv;
        }
        __syncthreads();

        // 5. publish h chunks (2ci, 2ci+1) of both group images
        if (tid < 32) {
            int q = tid & 1, b = (tid >> 1) & 7, img = tid >> 4;
            const __half* s = img ? hsml : hsmh;
            uint4 v = *(const uint4*)(s + b * 16 + q * 8);
            uint32_t off = (uint32_t)(((g * 2 + img) * 8 + b) * 1024 + (((2 * ci + q) ^ (b & 7)) << 4));
            *(uint4*)((char*)g_h2 + off) = v;
        }

        // 6. per-group grid barrier
        __syncthreads();
        if (tid == 0) {
            __threadfence();
            unsigned a = atomicAdd(barc, 1u);
            if (a == GRP - 1u) { *barc = 0u; st_release(genp, mygen + 1u); }
            else { while (ld_acquire(genp) == mygen) {} }
        }
        mygen++;
        __syncthreads();
    }
}

// ---------------------------------------------------------------------------
// mean over T + head GEMV
// ---------------------------------------------------------------------------
__global__ void pool_head_kernel(const float* __restrict__ head_w,
                                 const float* __restrict__ head_b,
                                 float* __restrict__ out) {
    int b = blockIdx.x;
    int h = threadIdx.x;
    __shared__ float feat[H_];
    const float* Yp = g_bufB + (size_t)b * T_ * H_;
    float s = 0.f;
    for (int t = 0; t < T_; ++t) s += Yp[t * H_ + h];
    feat[h] = s * (1.0f / (float)T_);
    __syncthreads();
    for (int cc = threadIdx.x; cc < NCLS; cc += blockDim.x) {
        float a = head_b[cc];
        const float* wr = head_w + cc * H_;
        for (int k = 0; k < H_; ++k) a += feat[k] * wr[k];
        out[b * NCLS + cc] = a;
    }
}

// ---------------------------------------------------------------------------
extern "C" void kernel_launch(void* const* d_in, const int* in_sizes, int n_in,
                              void* d_out, int out_size) {
    const float* x     = (const float*)d_in[0];
    const float* convw = (const float*)d_in[1];
    const float* gamma = (const float*)d_in[2];
    const float* beta  = (const float*)d_in[3];

    bool head_first = (in_sizes[4] == NCLS * H_);
    int o = head_first ? 6 : 4;
    const float* headw = (const float*)d_in[head_first ? 4 : 13];
    const float* headb = (const float*)d_in[head_first ? 5 : 14];
    const float* wih[3] = { (const float*)d_in[o + 0], (const float*)d_in[o + 3], (const float*)d_in[o + 6] };
    const float* whh[3] = { (const float*)d_in[o + 1], (const float*)d_in[o + 4], (const float*)d_in[o + 7] };
    const float* bb[3]  = { (const float*)d_in[o + 2], (const float*)d_in[o + 5], (const float*)d_in[o + 8] };

    static int smem_set = 0;
    if (!smem_set) {
        cudaFuncSetAttribute(lstm_kernel, cudaFuncAttributeMaxDynamicSharedMemorySize, SMEM_REQ);
        cudaFuncSetAttribute(xg_hmma_kernel, cudaFuncAttributeMaxDynamicSharedMemorySize, XG_SMEM_REQ);
        smem_set = 1;
    }

    void* xgsym = nullptr;   cudaGetSymbolAddress(&xgsym, g_xg);
    void* bufAsym = nullptr; cudaGetSymbolAddress(&bufAsym, g_bufA);
    void* bufBsym = nullptr; cudaGetSymbolAddress(&bufBsym, g_bufB);

    conv_kernel<<<B_ * NF, 128>>>(x, convw);
    gn_kernel<<<B_ * GN_G, 256>>>(gamma, beta);

    for (int layer = 1; layer <= 3; ++layer) {
        int din = (layer == 1) ? NF : H_;
        dim3 gg(G4H / 128, (B_ * T_) / 128);
        xg_hmma_kernel<<<gg, 256, XG_SMEM_REQ>>>(layer, wih[layer - 1], bb[layer - 1], din);
        float* yptr = (layer == 2) ? (float*)bufAsym : (float*)bufBsym;
        lstm_kernel<<<NBLK, THR, SMEM_REQ>>>(whh[layer - 1], (const float*)xgsym, yptr);
    }

    pool_head_kernel<<<B_, H_>>>(headw, headb, (float*)d_out);
}

// round 15
// speedup vs baseline: 1.0843x; 1.0089x over previous
#include <cuda_runtime.h>
#include <cuda_bf16.h>
#include <cuda_fp16.h>
#include <cstdint>

// ---------------------------------------------------------------------------
// MetaCNNLSTM: conv1d(64->256,k9,same) + GN(8)+ReLU -> 3x LSTM(512) -> mean -> head(50)
// B=32, T=512.
// LSTM: 4 independent groups of 8 batches; 32 persistent blocks/group (16 cells),
// compensated fp16 HMMA (3 passes), W-hi fragments in registers, flat atomic
// barrier, MUFU-minimized activation (R14-proven, 7166us base).
// NEW: double-buffered h image + DIRECT u16 publish from activation threads
// (removes staging phase + one __syncthreads; fixes latent WAR race).
// ---------------------------------------------------------------------------

#define B_      32
#define CIN     64
#define T_      512
#define NF      256
#define GN_G    8
#define KW      9
#define H_      512
#define G4H     2048
#define NCLS    50

#define NBLK    128            // 4 groups x 32 blocks
#define GRP     32
#define THR     256

// lstm dynamic smem layout (byte offsets from 1024-aligned base)
#define SM_WHI   0          // W hi: 64 rows x 64 chunks(16B) fp16, chunk^=(row&7)  65536
#define SM_WLO   65536      // W lo                                                 65536
#define SM_BHI   131072     // h hi: 8 rows x 64 chunks                              8192
#define SM_BLO   139264     // h lo (contiguous: one bulk copy)                      8192
#define SM_GSM   147456     // gates 2(k-half) x [64][10] fp32                       5120
#define SM_XGS   152576     // xg staging 2 x [8][64] fp32                           4096
#define SM_MBAR  156672     // mbarrier (8B)
#define SM_TOTAL 156680
#define SMEM_REQ (SM_TOTAL + 1024)

// xg HMMA kernel smem layout
#define XGS_AHI  0
#define XGS_ALO  32768
#define XGS_BHI  65536
#define XGS_BLO  98304
#define XG_SMEM_TOTAL 131072
#define XG_SMEM_REQ (XG_SMEM_TOTAL + 1024)

// ---- global scratch ----
__device__ float g_conv[B_ * NF * T_];
__device__ float g_bufA[B_ * T_ * H_];
__device__ float g_bufB[B_ * T_ * H_];
// [t][blk(128)][b_local(8)][gate*16+cl]  -- 2KB per (t, blk)
__device__ __align__(4096) float g_xg[T_ * NBLK * 8 * 64];
// h: [buf(2)][group(4)][img(2)][b_local(8) rows of 1024B, chunk k16^(b&7)] = 2 x 64KB
__device__ __align__(1024) __half g_h2[2 * 4 * 2 * 8 * 512];
// barrier counters/gens padded 128B apart (4 groups)
__device__ unsigned g_barc[4 * 32];
__device__ unsigned g_gen2[4 * 32];

// ---------------------------------------------------------------------------
// helpers
// ---------------------------------------------------------------------------
__device__ __forceinline__ unsigned ld_acquire(unsigned* p) {
    unsigned v;
    asm volatile("ld.acquire.gpu.global.u32 %0, [%1];" : "=r"(v) : "l"(p) : "memory");
    return v;
}
__device__ __forceinline__ void st_release(unsigned* p, unsigned v) {
    asm volatile("st.release.gpu.global.u32 [%0], %1;" :: "l"(p), "r"(v) : "memory");
}
__device__ __forceinline__ uint32_t smem_u32(const void* p) {
    uint32_t a;
    asm("{ .reg .u64 t; cvta.to.shared.u64 t, %1; cvt.u32.u64 %0, t; }" : "=r"(a) : "l"(p));
    return a;
}
__device__ __forceinline__ float rcp_fast(float x) {
    float r;
    asm("rcp.approx.f32 %0, %1;" : "=f"(r) : "f"(x));
    return r;
}
__device__ __forceinline__ uint32_t split_pair_h(float a, float b, uint32_t& lo_out) {
    __half ha = __float2half_rn(a), hb = __float2half_rn(b);
    float la = a - __half2float(ha);
    float lb = b - __half2float(hb);
    __half2 lo2 = __halves2half2(__float2half_rn(la), __float2half_rn(lb));
    __half2 hi2 = __halves2half2(ha, hb);
    lo_out = *reinterpret_cast<uint32_t*>(&lo2);
    return *reinterpret_cast<uint32_t*>(&hi2);
}
__device__ __forceinline__ void sts128(uint32_t addr, uint4 v) {
    asm volatile("st.shared.v4.b32 [%0], {%1,%2,%3,%4};"
                 :: "r"(addr), "r"(v.x), "r"(v.y), "r"(v.z), "r"(v.w) : "memory");
}
__device__ __forceinline__ void ldmatrix4(uint32_t& r0, uint32_t& r1, uint32_t& r2, uint32_t& r3, uint32_t addr) {
    asm volatile("ldmatrix.sync.aligned.m8n8.x4.shared.b16 {%0,%1,%2,%3}, [%4];"
                 : "=r"(r0), "=r"(r1), "=r"(r2), "=r"(r3) : "r"(addr));
}
__device__ __forceinline__ void ldmatrix2(uint32_t& r0, uint32_t& r1, uint32_t addr) {
    asm volatile("ldmatrix.sync.aligned.m8n8.x2.shared.b16 {%0,%1}, [%2];"
                 : "=r"(r0), "=r"(r1) : "r"(addr));
}
__device__ __forceinline__ void mma16816h(float* c, const uint32_t* a, uint32_t b0, uint32_t b1) {
    asm volatile("mma.sync.aligned.m16n8k16.row.col.f32.f16.f16.f32 "
                 "{%0,%1,%2,%3}, {%4,%5,%6,%7}, {%8,%9}, {%0,%1,%2,%3};"
                 : "+f"(c[0]), "+f"(c[1]), "+f"(c[2]), "+f"(c[3])
                 : "r"(a[0]), "r"(a[1]), "r"(a[2]), "r"(a[3]), "r"(b0), "r"(b1));
}

#define MBAR_WAIT(mbar, ph) do {                                                   \
    uint32_t _done;                                                                \
    asm volatile("{\n\t.reg .pred p;\n\t"                                          \
        "mbarrier.try_wait.parity.acquire.cta.shared::cta.b64 p, [%1], %2;\n\t"    \
        "selp.b32 %0, 1, 0, p;\n\t}"                                               \
        : "=r"(_done) : "r"(mbar), "r"(ph) : "memory");                            \
    if (!_done) {                                                                  \
        asm volatile("{\n\t.reg .pred P1;\n\t"                                     \
            "WL_%=:\n\t"                                                           \
            "mbarrier.try_wait.parity.acquire.cta.shared::cta.b64 P1, [%0], %1, 0x989680;\n\t" \
            "@P1 bra.uni WD_%=;\n\t"                                               \
            "bra.uni WL_%=;\n\t"                                                   \
            "WD_%=:\n\t}"                                                          \
            :: "r"(mbar), "r"(ph) : "memory");                                     \
    }                                                                              \
} while (0)

// ---------------------------------------------------------------------------
// conv1d
// ---------------------------------------------------------------------------
__global__ void conv_kernel(const float* __restrict__ x, const float* __restrict__ w) {
    int bf = blockIdx.x;
    int b = bf >> 8, f = bf & 255;
    __shared__ float wsh[CIN * KW];
    for (int e = threadIdx.x; e < CIN * KW; e += blockDim.x)
        wsh[e] = w[f * CIN * KW + e];
    __syncthreads();
    const float* xb = x + b * CIN * T_;
    #pragma unroll
    for (int tt = 0; tt < 4; ++tt) {
        int t = tt * 128 + threadIdx.x;
        float acc = 0.f;
        for (int c = 0; c < CIN; ++c) {
            const float* xr = xb + c * T_;
            const float* wr = wsh + c * KW;
            #pragma unroll
            for (int k = 0; k < KW; ++k) {
                int ti = t + k - 4;
                if (ti >= 0 && ti < T_) acc += xr[ti] * wr[k];
            }
        }
        g_conv[(b * NF + f) * T_ + t] = acc;
    }
}

// ---------------------------------------------------------------------------
// fused GroupNorm (stats + apply + ReLU + transpose -> g_bufA)
// ---------------------------------------------------------------------------
__global__ void gn_kernel(const float* __restrict__ gamma, const float* __restrict__ beta) {
    int bg = blockIdx.x;
    int b = bg >> 3, g = bg & 7;
    const float* base = g_conv + (b * NF + g * 32) * T_;
    float s = 0.f, ss = 0.f;
    for (int e = threadIdx.x; e < 32 * T_; e += blockDim.x) {
        float v = base[e];
        s += v; ss += v * v;
    }
    __shared__ float sh_s[256], sh_q[256];
    sh_s[threadIdx.x] = s; sh_q[threadIdx.x] = ss;
    __syncthreads();
    for (int st = 128; st > 0; st >>= 1) {
        if (threadIdx.x < st) {
            sh_s[threadIdx.x] += sh_s[threadIdx.x + st];
            sh_q[threadIdx.x] += sh_q[threadIdx.x + st];
        }
        __syncthreads();
    }
    __shared__ float sh_mu, sh_rs;
    if (threadIdx.x == 0) {
        float n = 32.0f * (float)T_;
        float mu = sh_s[0] / n;
        float var = sh_q[0] / n - mu * mu;
        sh_mu = mu;
        sh_rs = rsqrtf(var + 1e-5f);
    }
    __syncthreads();
    float mu = sh_mu, rs = sh_rs;
    for (int e = threadIdx.x; e < 32 * T_; e += blockDim.x) {
        int cl = e >> 9, t = e & 511;
        int f = g * 32 + cl;
        float v = (base[e] - mu) * rs * gamma[f] + beta[f];
        v = fmaxf(v, 0.f);
        g_bufA[(b * T_ + t) * NF + f] = v;
    }
}

// ---------------------------------------------------------------------------
// xg projection GEMM on HMMA (compensated fp16, 3 passes).
// output: g_xg[((t*128 + blk)*8 + b_local)*64 + gate*16 + cl]
//   blk = (b>>3)*32 + (cell>>4), b_local = b&7, cl = cell&15
// ---------------------------------------------------------------------------
__global__ __launch_bounds__(256) void xg_hmma_kernel(int layer,
                                                      const float* __restrict__ Wih,
                                                      const float* __restrict__ bias,
                                                      int Din) {
    const float* X = (layer == 2) ? g_bufB : g_bufA;
    extern __shared__ char smraw[];
    uint32_t rawa = smem_u32(smraw);
    uint32_t base = (rawa + 1023u) & ~1023u;
    uint32_t aHI = base + XGS_AHI;
    uint32_t aLO = base + XGS_ALO;
    uint32_t bHI = base + XGS_BHI;
    uint32_t bLO = base + XGS_BLO;

    const int tid = threadIdx.x;
    const int wid = tid >> 5, lane = tid & 31;
    const int n0 = blockIdx.x * 128, m0 = blockIdx.y * 128;

    const int wm = wid & 1, wn = wid >> 1;
    const int lrow = lane & 15, lk = lane >> 4;
    const int bcs = (lane >> 3) & 1;

    const int r = tid & 127, hf = tid >> 7;
    const int mg = m0 + r;
    const float* asrc0 = X + ((size_t)(mg & 31) * T_ + (mg >> 5)) * Din + hf * 64;
    const float* bsrc0 = Wih + (size_t)(n0 + r) * Din + hf * 64;
    const uint32_t stoff0 = (uint32_t)(r * 256);

    float acc[4][4][4];
    #pragma unroll
    for (int mi = 0; mi < 4; ++mi)
        #pragma unroll
        for (int ni = 0; ni < 4; ++ni)
            #pragma unroll
            for (int q = 0; q < 4; ++q) acc[mi][ni][q] = 0.f;

    const int nchunks = Din >> 7;
    for (int kc = 0; kc < nchunks; ++kc) {
        const float* asrc = asrc0 + kc * 128;
        const float* bsrc = bsrc0 + kc * 128;
        #pragma unroll
        for (int j = 0; j < 8; ++j) {
            int c = hf * 8 + j;
            uint32_t off = stoff0 + (uint32_t)(((c ^ (r & 7))) << 4);
            {
                float4 f0 = *(const float4*)(asrc + j * 8);
                float4 f1 = *(const float4*)(asrc + j * 8 + 4);
                uint4 vh, vl;
                vh.x = split_pair_h(f0.x, f0.y, vl.x);
                vh.y = split_pair_h(f0.z, f0.w, vl.y);
                vh.z = split_pair_h(f1.x, f1.y, vl.z);
                vh.w = split_pair_h(f1.z, f1.w, vl.w);
                sts128(aHI + off, vh);
                sts128(aLO + off, vl);
            }
            {
                float4 f0 = *(const float4*)(bsrc + j * 8);
                float4 f1 = *(const float4*)(bsrc + j * 8 + 4);
                uint4 vh, vl;
                vh.x = split_pair_h(f0.x, f0.y, vl.x);
                vh.y = split_pair_h(f0.z, f0.w, vl.y);
                vh.z = split_pair_h(f1.x, f1.y, vl.z);
                vh.w = split_pair_h(f1.z, f1.w, vl.w);
                sts128(bHI + off, vh);
                sts128(bLO + off, vl);
            }
        }
        __syncthreads();

        #pragma unroll
        for (int s = 0; s < 8; ++s) {
            uint32_t ahf[4][4], alf[4][4], bhf[4][2], blf[4][2];
            #pragma unroll
            for (int mi = 0; mi < 4; ++mi) {
                int rowA = wm * 64 + mi * 16 + lrow;
                uint32_t aoff = (uint32_t)(rowA * 256 + (((2 * s + lk) ^ (rowA & 7)) << 4));
                ldmatrix4(ahf[mi][0], ahf[mi][1], ahf[mi][2], ahf[mi][3], aHI + aoff);
                ldmatrix4(alf[mi][0], alf[mi][1], alf[mi][2], alf[mi][3], aLO + aoff);
            }
            #pragma unroll
            for (int ni = 0; ni < 4; ++ni) {
                int rowB = wn * 32 + ni * 8 + (lane & 7);
                uint32_t boff = (uint32_t)(rowB * 256 + (((2 * s + bcs) ^ (rowB & 7)) << 4));
                ldmatrix2(bhf[ni][0], bhf[ni][1], bHI + boff);
                ldmatrix2(blf[ni][0], blf[ni][1], bLO + boff);
            }
            #pragma unroll
            for (int mi = 0; mi < 4; ++mi)
                #pragma unroll
                for (int ni = 0; ni < 4; ++ni) {
                    mma16816h(acc[mi][ni], ahf[mi], bhf[ni][0], bhf[ni][1]);
                    mma16816h(acc[mi][ni], ahf[mi], blf[ni][0], blf[ni][1]);
                    mma16816h(acc[mi][ni], alf[mi], bhf[ni][0], bhf[ni][1]);
                }
        }
        __syncthreads();
    }

    #pragma unroll
    for (int mi = 0; mi < 4; ++mi) {
        #pragma unroll
        for (int ni = 0; ni < 4; ++ni) {
            int cb = n0 + wn * 32 + ni * 8 + (lane & 3) * 2;
            int gate = cb >> 9, cell = cb & 511;
            int cblk = cell >> 4, cl = cell & 15;
            float bz0 = bias[cb], bz1 = bias[cb + 1];
            #pragma unroll
            for (int hrow = 0; hrow < 2; ++hrow) {
                int row = m0 + wm * 64 + mi * 16 + (lane >> 2) + hrow * 8;
                int t = row >> 5, b = row & 31;
                int blk = (b >> 3) * 32 + cblk;
                float2 v = make_float2(acc[mi][ni][hrow * 2 + 0] + bz0,
                                       acc[mi][ni][hrow * 2 + 1] + bz1);
                *(float2*)&g_xg[(((size_t)t * NBLK + blk) * 8 + (b & 7)) * 64 + gate * 16 + cl] = v;
            }
        }
    }
}

// ---------------------------------------------------------------------------
// persistent HMMA LSTM: 4 groups x 32 blocks. Block bx: group g=bx>>5 (batches
// g*8..+8), cells (bx&31)*16..+16. A row r <-> (gate=r&3, cell=c0+(r>>2)).
// 8 warps = 4(m16) x 2(k-half); N=8 whole. k-halves reduced in smem.
// Double-buffered h; direct u16 publish from activation threads.
// ---------------------------------------------------------------------------
__global__ __launch_bounds__(THR, 1) void lstm_kernel(const float* __restrict__ Whh,
                                                      const float* __restrict__ xg,
                                                      float* __restrict__ Y) {
    extern __shared__ char smraw[];
    uint32_t rawa = smem_u32(smraw);
    uint32_t base = (rawa + 1023u) & ~1023u;
    char* sbase = smraw + (base - rawa);
    uint32_t wHI  = base + SM_WHI;
    uint32_t wLO  = base + SM_WLO;
    uint32_t bHI  = base + SM_BHI;
    float*   gsm  = (float*)(sbase + SM_GSM);
    float*   xgs  = (float*)(sbase + SM_XGS);
    uint32_t mbar = base + SM_MBAR;
    uint32_t xgs_a = base + SM_XGS;

    const int tid = threadIdx.x;
    const int bx = blockIdx.x;
    const int g  = bx >> 5;            // batch group (0..3)
    const int ci = bx & 31;            // cell-block index (0..31)
    const int c0 = ci * 16;
    const int wid = tid >> 5, lane = tid & 31;

    unsigned* barc = &g_barc[g * 32];
    unsigned* genp = &g_gen2[g * 32];
    unsigned mygen = *((volatile unsigned*)genp);

    if (tid == 0) {
        asm volatile("mbarrier.init.shared.b64 [%0], %1;" :: "r"(mbar), "r"(1u) : "memory");
    }

    // --- stage W tile: 64 rows x 64 chunks(16B), fp32 -> fp16 hi/lo, chunk^=(row&7) ---
    #pragma unroll
    for (int i = 0; i < 16; ++i) {
        int gg = tid + i * 256;           // 4096 chunks
        int r = gg >> 6, k16 = gg & 63;
        int j = (r & 3) * 512 + c0 + (r >> 2);
        const float* src = Whh + (size_t)j * 512 + k16 * 8;
        float4 f0 = *(const float4*)(src);
        float4 f1 = *(const float4*)(src + 4);
        uint4 vh, vl;
        vh.x = split_pair_h(f0.x, f0.y, vl.x);
        vh.y = split_pair_h(f0.z, f0.w, vl.y);
        vh.z = split_pair_h(f1.x, f1.y, vl.z);
        vh.w = split_pair_h(f1.z, f1.w, vl.w);
        uint32_t off = (uint32_t)((r << 10) + (((k16 ^ (r & 7))) << 4));
        sts128(wHI + off, vh);
        sts128(wLO + off, vl);
    }

    // --- zero this block's chunks (2ci, 2ci+1) of both images in h-buffer 0 ---
    if (tid < 32) {
        int q = tid & 1, b = (tid >> 1) & 7, img = tid >> 4;
        uint32_t off = (uint32_t)(((g * 2 + img) * 8 + b) * 1024 + (((2 * ci + q) ^ (b & 7)) << 4));
        *(uint4*)((char*)g_h2 + off) = make_uint4(0, 0, 0, 0);
    }
    __syncthreads();

    // GEMM thread mapping: 4m x 2k
    const int wm = wid & 3, wk = wid >> 2;
    const int lrow = lane & 15, lk = lane >> 4;
    const uint32_t arowoff = (uint32_t)(((wm * 16 + lrow) << 10));
    const int ax7 = lrow & 7;

    // --- hoist W-hi fragments (this warp's k-half) into registers ---
    uint32_t AH[16][4];
    #pragma unroll
    for (int ks = 0; ks < 16; ++ks) {
        int ch = (wk * 16 + ks) * 2 + lk;
        uint32_t aoff = (uint32_t)(((ch ^ ax7)) << 4);
        ldmatrix4(AH[ks][0], AH[ks][1], AH[ks][2], AH[ks][3], wHI + arowoff + aoff);
    }

    // --- prologue: prefetch xg(0) + per-group initial barrier ---
    if (tid == 0) {
        asm volatile("mbarrier.arrive.expect_tx.shared.b64 _, [%0], %1;"
                     :: "r"(mbar), "r"(2048u) : "memory");
        asm volatile("cp.async.bulk.shared::cluster.global.mbarrier::complete_tx::bytes "
                     "[%0], [%1], %2, [%3];"
                     :: "r"(xgs_a), "l"((const char*)(xg + (size_t)bx * 512)), "r"(2048u), "r"(mbar) : "memory");
        __threadfence();
        unsigned a = atomicAdd(barc, 1u);
        if (a == GRP - 1u) { *barc = 0u; st_release(genp, mygen + 1u); }
        else { while (ld_acquire(genp) == mygen) {} }
    }
    mygen++;
    __syncthreads();
    MBAR_WAIT(mbar, 0u);

    // B-frag addressing (8 batch rows)
    const int brow = lane & 7;
    const uint32_t browoff = (uint32_t)(brow << 10);
    const int bx7 = brow;
    const int bcs = (lane >> 3) & 1;

    // activation mapping: cl = tid>>3 (0..15), b_local = tid&7  (tid < 128)
    const int cl = tid >> 3;
    const int bb = tid & 7;
    float cst = 0.f;
    // direct-publish address (hi image; lo at +8192) within a 64KB h-buffer
    const uint32_t pub_base = (uint32_t)(((g * 2 + 0) * 8 + bb) * 1024
                                         + (((2 * ci + (cl >> 3)) ^ (bb & 7)) << 4) + (cl & 7) * 2);

    const char* hsrc0 = (const char*)g_h2 + g * 16384;
    const float L2E = 1.4426950408889634f;

    for (int t = 0; t < T_; ++t) {
        // 1. bulk copies from h-buffer t&1: h hi+lo (16KB) + xg(t+1) (2KB)
        if (tid == 0) {
            unsigned txb = 16384u + ((t + 1 < T_) ? 2048u : 0u);
            asm volatile("mbarrier.arrive.expect_tx.shared.b64 _, [%0], %1;"
                         :: "r"(mbar), "r"(txb) : "memory");
            asm volatile("cp.async.bulk.shared::cluster.global.mbarrier::complete_tx::bytes "
                         "[%0], [%1], %2, [%3];"
                         :: "r"(bHI), "l"(hsrc0 + (size_t)(t & 1) * 65536), "r"(16384u), "r"(mbar) : "memory");
            if (t + 1 < T_) {
                const char* xsrc = (const char*)(xg + (((size_t)(t + 1) * NBLK + bx) * 512));
                asm volatile("cp.async.bulk.shared::cluster.global.mbarrier::complete_tx::bytes "
                             "[%0], [%1], %2, [%3];"
                             :: "r"(xgs_a + (((t + 1) & 1) ? 2048u : 0u)), "l"(xsrc), "r"(2048u), "r"(mbar) : "memory");
            }
        }
        MBAR_WAIT(mbar, (uint32_t)((t + 1) & 1));

        // 2. GEMM: 16 k-steps (this warp's half), 3 accumulator chains
        float acc_a[4] = {0.f, 0.f, 0.f, 0.f};
        float acc_b[4] = {0.f, 0.f, 0.f, 0.f};
        float acc_c[4] = {0.f, 0.f, 0.f, 0.f};
        #pragma unroll
        for (int ks = 0; ks < 16; ++ks) {
            int chA = (wk * 16 + ks) * 2 + lk;
            int chB = (wk * 16 + ks) * 2 + bcs;
            uint32_t aoff = (uint32_t)(((chA ^ ax7)) << 4);
            uint32_t boff = (uint32_t)(((chB ^ bx7)) << 4);
            uint32_t al0, al1, al2, al3;
            uint32_t bh0, bh1, bl0, bl1;
            ldmatrix4(al0, al1, al2, al3, wLO + arowoff + aoff);
            ldmatrix2(bh0, bh1, bHI + browoff + boff);
            ldmatrix2(bl0, bl1, (bHI + 8192u) + browoff + boff);
            mma16816h(acc_a, AH[ks], bh0, bh1);
            mma16816h(acc_b, AH[ks], bl0, bl1);
            uint32_t alr[4] = {al0, al1, al2, al3};
            mma16816h(acc_c, alr, bh0, bh1);
        }

        // 3. combine + store per-k-half gates to gsm[wk] ([64][10])
        {
            int r0 = wm * 16 + (lane >> 2);
            int cb = (lane & 3) * 2;
            float* gk = gsm + wk * 640;
            float s0 = acc_a[0] + acc_b[0] + acc_c[0];
            float s1 = acc_a[1] + acc_b[1] + acc_c[1];
            float s2 = acc_a[2] + acc_b[2] + acc_c[2];
            float s3 = acc_a[3] + acc_b[3] + acc_c[3];
            *(float2*)&gk[r0 * 10 + cb]       = make_float2(s0, s1);
            *(float2*)&gk[(r0 + 8) * 10 + cb] = make_float2(s2, s3);
        }
        __syncthreads();

        // 4. activation (MUFU-minimized) + DIRECT publish into h-buffer (t+1)&1
        if (tid < 128) {
            const float* xb2 = xgs + ((t & 1) ? 512 : 0) + bb * 64;
            int r = cl * 4;
            float gi = gsm[(r + 0) * 10 + bb] + gsm[640 + (r + 0) * 10 + bb] + xb2[cl];
            float gf = gsm[(r + 1) * 10 + bb] + gsm[640 + (r + 1) * 10 + bb] + xb2[16 + cl];
            float gg = gsm[(r + 2) * 10 + bb] + gsm[640 + (r + 2) * 10 + bb] + xb2[32 + cl];
            float go = gsm[(r + 3) * 10 + bb] + gsm[640 + (r + 3) * 10 + bb] + xb2[48 + cl];

            float xi = fminf(fmaxf(gi, -15.f), 15.f);
            float xf = fminf(fmaxf(gf, -15.f), 15.f);
            float xgc = fminf(fmaxf(gg, -7.5f), 7.5f);
            float ea = exp2f(-xi * L2E);
            float eb = exp2f(-xf * L2E);
            float eu = exp2f(xgc * (2.f * L2E));
            float aa = 1.f + ea, bbv = 1.f + eb, uu = 1.f + eu;
            float p2 = aa * bbv;
            float r3 = rcp_fast(p2 * uu);
            float inv_u = r3 * p2;
            float r2 = r3 * uu;
            float iv = r2 * bbv;
            float fv = r2 * aa;
            float gv = 1.f - 2.f * inv_u;
            cst = fv * cst + iv * gv;

            float xo = fminf(fmaxf(go, -15.f), 15.f);
            float xc = fminf(fmaxf(cst, -7.5f), 7.5f);
            float ed = exp2f(-xo * L2E);
            float ev = exp2f(xc * (2.f * L2E));
            float dd = 1.f + ed, vv = 1.f + ev;
            float rq = rcp_fast(dd * vv);
            float inv_v = rq * dd;
            float ov = rq * vv;
            float hv = ov * (1.f - 2.f * inv_v);

            __half hh = __float2half_rn(hv);
            __half hl = __float2half_rn(hv - __half2float(hh));
            char* pb = (char*)g_h2 + (size_t)((t + 1) & 1) * 65536 + pub_base;
            *(__half*)pb = hh;
            *(__half*)(pb + 8192) = hl;
            Y[((size_t)(g * 8 + bb) * T_ + t) * H_ + c0 + cl] = hv;
        }

        // 5. per-group grid barrier
        __syncthreads();
        if (tid == 0) {
            __threadfence();
            unsigned a = atomicAdd(barc, 1u);
            if (a == GRP - 1u) { *barc = 0u; st_release(genp, mygen + 1u); }
            else { while (ld_acquire(genp) == mygen) {} }
        }
        mygen++;
        __syncthreads();
    }
}

// ---------------------------------------------------------------------------
// mean over T + head GEMV
// ---------------------------------------------------------------------------
__global__ void pool_head_kernel(const float* __restrict__ head_w,
                                 const float* __restrict__ head_b,
                                 float* __restrict__ out) {
    int b = blockIdx.x;
    int h = threadIdx.x;
    __shared__ float feat[H_];
    const float* Yp = g_bufB + (size_t)b * T_ * H_;
    float s = 0.f;
    for (int t = 0; t < T_; ++t) s += Yp[t * H_ + h];
    feat[h] = s * (1.0f / (float)T_);
    __syncthreads();
    for (int cc = threadIdx.x; cc < NCLS; cc += blockDim.x) {
        float a = head_b[cc];
        const float* wr = head_w + cc * H_;
        for (int k = 0; k < H_; ++k) a += feat[k] * wr[k];
        out[b * NCLS + cc] = a;
    }
}

// ---------------------------------------------------------------------------
extern "C" void kernel_launch(void* const* d_in, const int* in_sizes, int n_in,
                              void* d_out, int out_size) {
    const float* x     = (const float*)d_in[0];
    const float* convw = (const float*)d_in[1];
    const float* gamma = (const float*)d_in[2];
    const float* beta  = (const float*)d_in[3];

    bool head_first = (in_sizes[4] == NCLS * H_);
    int o = head_first ? 6 : 4;
    const float* headw = (const float*)d_in[head_first ? 4 : 13];
    const float* headb = (const float*)d_in[head_first ? 5 : 14];
    const float* wih[3] = { (const float*)d_in[o + 0], (const float*)d_in[o + 3], (const float*)d_in[o + 6] };
    const float* whh[3] = { (const float*)d_in[o + 1], (const float*)d_in[o + 4], (const float*)d_in[o + 7] };
    const float* bb[3]  = { (const float*)d_in[o + 2], (const float*)d_in[o + 5], (const float*)d_in[o + 8] };

    static int smem_set = 0;
    if (!smem_set) {
        cudaFuncSetAttribute(lstm_kernel, cudaFuncAttributeMaxDynamicSharedMemorySize, SMEM_REQ);
        cudaFuncSetAttribute(xg_hmma_kernel, cudaFuncAttributeMaxDynamicSharedMemorySize, XG_SMEM_REQ);
        smem_set = 1;
    }

    void* xgsym = nullptr;   cudaGetSymbolAddress(&xgsym, g_xg);
    void* bufAsym = nullptr; cudaGetSymbolAddress(&bufAsym, g_bufA);
    void* bufBsym = nullptr; cudaGetSymbolAddress(&bufBsym, g_bufB);

    conv_kernel<<<B_ * NF, 128>>>(x, convw);
    gn_kernel<<<B_ * GN_G, 256>>>(gamma, beta);

    for (int layer = 1; layer <= 3; ++layer) {
        int din = (layer == 1) ? NF : H_;
        dim3 gg(G4H / 128, (B_ * T_) / 128);
        xg_hmma_kernel<<<gg, 256, XG_SMEM_REQ>>>(layer, wih[layer - 1], bb[layer - 1], din);
        float* yptr = (layer == 2) ? (float*)bufAsym : (float*)bufBsym;
        lstm_kernel<<<NBLK, THR, SMEM_REQ>>>(whh[layer - 1], (const float*)xgsym, yptr);
    }

    pool_head_kernel<<<B_, H_>>>(headw, headb, (float*)d_out);
}

// round 16
// speedup vs baseline: 1.0870x; 1.0024x over previous
#include <cuda_runtime.h>
#include <cuda_bf16.h>
#include <cuda_fp16.h>
#include <cstdint>

// ---------------------------------------------------------------------------
// MetaCNNLSTM: conv1d(64->256,k9,same) + GN(8)+ReLU -> 3x LSTM(512) -> mean -> head(50)
// B=32, T=512.
// LSTM: 4 independent groups of 8 batches; 32 persistent blocks/group (16 cells),
// compensated fp16 HMMA (3 passes), W-hi fragments in registers, flat atomic
// barrier, MUFU-minimized activation (R14-proven, 7166us base).
// NEW: double-buffered h image + DIRECT u16 publish from activation threads
// (removes staging phase + one __syncthreads; fixes latent WAR race).
// ---------------------------------------------------------------------------

#define B_      32
#define CIN     64
#define T_      512
#define NF      256
#define GN_G    8
#define KW      9
#define H_      512
#define G4H     2048
#define NCLS    50

#define NBLK    128            // 4 groups x 32 blocks
#define GRP     32
#define THR     256

// lstm dynamic smem layout (byte offsets from 1024-aligned base)
#define SM_WHI   0          // W hi: 64 rows x 64 chunks(16B) fp16, chunk^=(row&7)  65536
#define SM_WLO   65536      // W lo                                                 65536
#define SM_BHI   131072     // h hi: 8 rows x 64 chunks                              8192
#define SM_BLO   139264     // h lo (contiguous: one bulk copy)                      8192
#define SM_GSM   147456     // gates 2(k-half) x [64][10] fp32                       5120
#define SM_XGS   152576     // xg staging 2 x [8][64] fp32                           4096
#define SM_MBAR  156672     // mbarrier (8B)
#define SM_TOTAL 156680
#define SMEM_REQ (SM_TOTAL + 1024)

// xg HMMA kernel smem layout
#define XGS_AHI  0
#define XGS_ALO  32768
#define XGS_BHI  65536
#define XGS_BLO  98304
#define XG_SMEM_TOTAL 131072
#define XG_SMEM_REQ (XG_SMEM_TOTAL + 1024)

// ---- global scratch ----
__device__ float g_conv[B_ * NF * T_];
__device__ float g_bufA[B_ * T_ * H_];
__device__ float g_bufB[B_ * T_ * H_];
// [t][blk(128)][b_local(8)][gate*16+cl]  -- 2KB per (t, blk)
__device__ __align__(4096) float g_xg[T_ * NBLK * 8 * 64];
// h: [buf(2)][group(4)][img(2)][b_local(8) rows of 1024B, chunk k16^(b&7)] = 2 x 64KB
__device__ __align__(1024) __half g_h2[2 * 4 * 2 * 8 * 512];
// barrier counters/gens padded 128B apart (4 groups)
__device__ unsigned g_barc[4 * 32];
__device__ unsigned g_gen2[4 * 32];

// ---------------------------------------------------------------------------
// helpers
// ---------------------------------------------------------------------------
__device__ __forceinline__ unsigned ld_acquire(unsigned* p) {
    unsigned v;
    asm volatile("ld.acquire.gpu.global.u32 %0, [%1];" : "=r"(v) : "l"(p) : "memory");
    return v;
}
__device__ __forceinline__ void st_release(unsigned* p, unsigned v) {
    asm volatile("st.release.gpu.global.u32 [%0], %1;" :: "l"(p), "r"(v) : "memory");
}
__device__ __forceinline__ uint32_t smem_u32(const void* p) {
    uint32_t a;
    asm("{ .reg .u64 t; cvta.to.shared.u64 t, %1; cvt.u32.u64 %0, t; }" : "=r"(a) : "l"(p));
    return a;
}
__device__ __forceinline__ float rcp_fast(float x) {
    float r;
    asm("rcp.approx.f32 %0, %1;" : "=f"(r) : "f"(x));
    return r;
}
__device__ __forceinline__ uint32_t split_pair_h(float a, float b, uint32_t& lo_out) {
    __half ha = __float2half_rn(a), hb = __float2half_rn(b);
    float la = a - __half2float(ha);
    float lb = b - __half2float(hb);
    __half2 lo2 = __halves2half2(__float2half_rn(la), __float2half_rn(lb));
    __half2 hi2 = __halves2half2(ha, hb);
    lo_out = *reinterpret_cast<uint32_t*>(&lo2);
    return *reinterpret_cast<uint32_t*>(&hi2);
}
__device__ __forceinline__ void sts128(uint32_t addr, uint4 v) {
    asm volatile("st.shared.v4.b32 [%0], {%1,%2,%3,%4};"
                 :: "r"(addr), "r"(v.x), "r"(v.y), "r"(v.z), "r"(v.w) : "memory");
}
__device__ __forceinline__ void ldmatrix4(uint32_t& r0, uint32_t& r1, uint32_t& r2, uint32_t& r3, uint32_t addr) {
    asm volatile("ldmatrix.sync.aligned.m8n8.x4.shared.b16 {%0,%1,%2,%3}, [%4];"
                 : "=r"(r0), "=r"(r1), "=r"(r2), "=r"(r3) : "r"(addr));
}
__device__ __forceinline__ void ldmatrix2(uint32_t& r0, uint32_t& r1, uint32_t addr) {
    asm volatile("ldmatrix.sync.aligned.m8n8.x2.shared.b16 {%0,%1}, [%2];"
                 : "=r"(r0), "=r"(r1) : "r"(addr));
}
__device__ __forceinline__ void mma16816h(float* c, const uint32_t* a, uint32_t b0, uint32_t b1) {
    asm volatile("mma.sync.aligned.m16n8k16.row.col.f32.f16.f16.f32 "
                 "{%0,%1,%2,%3}, {%4,%5,%6,%7}, {%8,%9}, {%0,%1,%2,%3};"
                 : "+f"(c[0]), "+f"(c[1]), "+f"(c[2]), "+f"(c[3])
                 : "r"(a[0]), "r"(a[1]), "r"(a[2]), "r"(a[3]), "r"(b0), "r"(b1));
}

#define MBAR_WAIT(mbar, ph) do {                                                   \
    uint32_t _done;                                                                \
    asm volatile("{\n\t.reg .pred p;\n\t"                                          \
        "mbarrier.try_wait.parity.acquire.cta.shared::cta.b64 p, [%1], %2;\n\t"    \
        "selp.b32 %0, 1, 0, p;\n\t}"                                               \
        : "=r"(_done) : "r"(mbar), "r"(ph) : "memory");                            \
    if (!_done) {                                                                  \
        asm volatile("{\n\t.reg .pred P1;\n\t"                                     \
            "WL_%=:\n\t"                                                           \
            "mbarrier.try_wait.parity.acquire.cta.shared::cta.b64 P1, [%0], %1, 0x989680;\n\t" \
            "@P1 bra.uni WD_%=;\n\t"                                               \
            "bra.uni WL_%=;\n\t"                                                   \
            "WD_%=:\n\t}"                                                          \
            :: "r"(mbar), "r"(ph) : "memory");                                     \
    }                                                                              \
} while (0)

// ---------------------------------------------------------------------------
// conv1d
// ---------------------------------------------------------------------------
__global__ void conv_kernel(const float* __restrict__ x, const float* __restrict__ w) {
    int bf = blockIdx.x;
    int b = bf >> 8, f = bf & 255;
    __shared__ float wsh[CIN * KW];
    for (int e = threadIdx.x; e < CIN * KW; e += blockDim.x)
        wsh[e] = w[f * CIN * KW + e];
    __syncthreads();
    const float* xb = x + b * CIN * T_;
    #pragma unroll
    for (int tt = 0; tt < 4; ++tt) {
        int t = tt * 128 + threadIdx.x;
        float acc = 0.f;
        for (int c = 0; c < CIN; ++c) {
            const float* xr = xb + c * T_;
            const float* wr = wsh + c * KW;
            #pragma unroll
            for (int k = 0; k < KW; ++k) {
                int ti = t + k - 4;
                if (ti >= 0 && ti < T_) acc += xr[ti] * wr[k];
            }
        }
        g_conv[(b * NF + f) * T_ + t] = acc;
    }
}

// ---------------------------------------------------------------------------
// fused GroupNorm (stats + apply + ReLU + transpose -> g_bufA)
// ---------------------------------------------------------------------------
__global__ void gn_kernel(const float* __restrict__ gamma, const float* __restrict__ beta) {
    int bg = blockIdx.x;
    int b = bg >> 3, g = bg & 7;
    const float* base = g_conv + (b * NF + g * 32) * T_;
    float s = 0.f, ss = 0.f;
    for (int e = threadIdx.x; e < 32 * T_; e += blockDim.x) {
        float v = base[e];
        s += v; ss += v * v;
    }
    __shared__ float sh_s[256], sh_q[256];
    sh_s[threadIdx.x] = s; sh_q[threadIdx.x] = ss;
    __syncthreads();
    for (int st = 128; st > 0; st >>= 1) {
        if (threadIdx.x < st) {
            sh_s[threadIdx.x] += sh_s[threadIdx.x + st];
            sh_q[threadIdx.x] += sh_q[threadIdx.x + st];
        }
        __syncthreads();
    }
    __shared__ float sh_mu, sh_rs;
    if (threadIdx.x == 0) {
        float n = 32.0f * (float)T_;
        float mu = sh_s[0] / n;
        float var = sh_q[0] / n - mu * mu;
        sh_mu = mu;
        sh_rs = rsqrtf(var + 1e-5f);
    }
    __syncthreads();
    float mu = sh_mu, rs = sh_rs;
    for (int e = threadIdx.x; e < 32 * T_; e += blockDim.x) {
        int cl = e >> 9, t = e & 511;
        int f = g * 32 + cl;
        float v = (base[e] - mu) * rs * gamma[f] + beta[f];
        v = fmaxf(v, 0.f);
        g_bufA[(b * T_ + t) * NF + f] = v;
    }
}

// ---------------------------------------------------------------------------
// xg projection GEMM on HMMA (compensated fp16, 3 passes).
// output: g_xg[((t*128 + blk)*8 + b_local)*64 + gate*16 + cl]
//   blk = (b>>3)*32 + (cell>>4), b_local = b&7, cl = cell&15
// ---------------------------------------------------------------------------
__global__ __launch_bounds__(256) void xg_hmma_kernel(int layer,
                                                      const float* __restrict__ Wih,
                                                      const float* __restrict__ bias,
                                                      int Din) {
    const float* X = (layer == 2) ? g_bufB : g_bufA;
    extern __shared__ char smraw[];
    uint32_t rawa = smem_u32(smraw);
    uint32_t base = (rawa + 1023u) & ~1023u;
    uint32_t aHI = base + XGS_AHI;
    uint32_t aLO = base + XGS_ALO;
    uint32_t bHI = base + XGS_BHI;
    uint32_t bLO = base + XGS_BLO;

    const int tid = threadIdx.x;
    const int wid = tid >> 5, lane = tid & 31;
    const int n0 = blockIdx.x * 128, m0 = blockIdx.y * 128;

    const int wm = wid & 1, wn = wid >> 1;
    const int lrow = lane & 15, lk = lane >> 4;
    const int bcs = (lane >> 3) & 1;

    const int r = tid & 127, hf = tid >> 7;
    const int mg = m0 + r;
    const float* asrc0 = X + ((size_t)(mg & 31) * T_ + (mg >> 5)) * Din + hf * 64;
    const float* bsrc0 = Wih + (size_t)(n0 + r) * Din + hf * 64;
    const uint32_t stoff0 = (uint32_t)(r * 256);

    float acc[4][4][4];
    #pragma unroll
    for (int mi = 0; mi < 4; ++mi)
        #pragma unroll
        for (int ni = 0; ni < 4; ++ni)
            #pragma unroll
            for (int q = 0; q < 4; ++q) acc[mi][ni][q] = 0.f;

    const int nchunks = Din >> 7;
    for (int kc = 0; kc < nchunks; ++kc) {
        const float* asrc = asrc0 + kc * 128;
        const float* bsrc = bsrc0 + kc * 128;
        #pragma unroll
        for (int j = 0; j < 8; ++j) {
            int c = hf * 8 + j;
            uint32_t off = stoff0 + (uint32_t)(((c ^ (r & 7))) << 4);
            {
                float4 f0 = *(const float4*)(asrc + j * 8);
                float4 f1 = *(const float4*)(asrc + j * 8 + 4);
                uint4 vh, vl;
                vh.x = split_pair_h(f0.x, f0.y, vl.x);
                vh.y = split_pair_h(f0.z, f0.w, vl.y);
                vh.z = split_pair_h(f1.x, f1.y, vl.z);
                vh.w = split_pair_h(f1.z, f1.w, vl.w);
                sts128(aHI + off, vh);
                sts128(aLO + off, vl);
            }
            {
                float4 f0 = *(const float4*)(bsrc + j * 8);
                float4 f1 = *(const float4*)(bsrc + j * 8 + 4);
                uint4 vh, vl;
                vh.x = split_pair_h(f0.x, f0.y, vl.x);
                vh.y = split_pair_h(f0.z, f0.w, vl.y);
                vh.z = split_pair_h(f1.x, f1.y, vl.z);
                vh.w = split_pair_h(f1.z, f1.w, vl.w);
                sts128(bHI + off, vh);
                sts128(bLO + off, vl);
            }
        }
        __syncthreads();

        #pragma unroll
        for (int s = 0; s < 8; ++s) {
            uint32_t ahf[4][4], alf[4][4], bhf[4][2], blf[4][2];
            #pragma unroll
            for (int mi = 0; mi < 4; ++mi) {
                int rowA = wm * 64 + mi * 16 + lrow;
                uint32_t aoff = (uint32_t)(rowA * 256 + (((2 * s + lk) ^ (rowA & 7)) << 4));
                ldmatrix4(ahf[mi][0], ahf[mi][1], ahf[mi][2], ahf[mi][3], aHI + aoff);
                ldmatrix4(alf[mi][0], alf[mi][1], alf[mi][2], alf[mi][3], aLO + aoff);
            }
            #pragma unroll
            for (int ni = 0; ni < 4; ++ni) {
                int rowB = wn * 32 + ni * 8 + (lane & 7);
                uint32_t boff = (uint32_t)(rowB * 256 + (((2 * s + bcs) ^ (rowB & 7)) << 4));
                ldmatrix2(bhf[ni][0], bhf[ni][1], bHI + boff);
                ldmatrix2(blf[ni][0], blf[ni][1], bLO + boff);
            }
            #pragma unroll
            for (int mi = 0; mi < 4; ++mi)
                #pragma unroll
                for (int ni = 0; ni < 4; ++ni) {
                    mma16816h(acc[mi][ni], ahf[mi], bhf[ni][0], bhf[ni][1]);
                    mma16816h(acc[mi][ni], ahf[mi], blf[ni][0], blf[ni][1]);
                    mma16816h(acc[mi][ni], alf[mi], bhf[ni][0], bhf[ni][1]);
                }
        }
        __syncthreads();
    }

    #pragma unroll
    for (int mi = 0; mi < 4; ++mi) {
        #pragma unroll
        for (int ni = 0; ni < 4; ++ni) {
            int cb = n0 + wn * 32 + ni * 8 + (lane & 3) * 2;
            int gate = cb >> 9, cell = cb & 511;
            int cblk = cell >> 4, cl = cell & 15;
            float bz0 = bias[cb], bz1 = bias[cb + 1];
            #pragma unroll
            for (int hrow = 0; hrow < 2; ++hrow) {
                int row = m0 + wm * 64 + mi * 16 + (lane >> 2) + hrow * 8;
                int t = row >> 5, b = row & 31;
                int blk = (b >> 3) * 32 + cblk;
                float2 v = make_float2(acc[mi][ni][hrow * 2 + 0] + bz0,
                                       acc[mi][ni][hrow * 2 + 1] + bz1);
                *(float2*)&g_xg[(((size_t)t * NBLK + blk) * 8 + (b & 7)) * 64 + gate * 16 + cl] = v;
            }
        }
    }
}

// ---------------------------------------------------------------------------
// persistent HMMA LSTM: 4 groups x 32 blocks. Block bx: group g=bx>>5 (batches
// g*8..+8), cells (bx&31)*16..+16. A row r <-> (gate=r&3, cell=c0+(r>>2)).
// 8 warps = 4(m16) x 2(k-half); N=8 whole. k-halves reduced in smem.
// Double-buffered h; direct u16 publish from activation threads.
// ---------------------------------------------------------------------------
__global__ __launch_bounds__(THR, 1) void lstm_kernel(const float* __restrict__ Whh,
                                                      const float* __restrict__ xg,
                                                      float* __restrict__ Y) {
    extern __shared__ char smraw[];
    uint32_t rawa = smem_u32(smraw);
    uint32_t base = (rawa + 1023u) & ~1023u;
    char* sbase = smraw + (base - rawa);
    uint32_t wHI  = base + SM_WHI;
    uint32_t wLO  = base + SM_WLO;
    uint32_t bHI  = base + SM_BHI;
    float*   gsm  = (float*)(sbase + SM_GSM);
    float*   xgs  = (float*)(sbase + SM_XGS);
    uint32_t mbar = base + SM_MBAR;
    uint32_t xgs_a = base + SM_XGS;

    const int tid = threadIdx.x;
    const int bx = blockIdx.x;
    const int g  = bx >> 5;            // batch group (0..3)
    const int ci = bx & 31;            // cell-block index (0..31)
    const int c0 = ci * 16;
    const int wid = tid >> 5, lane = tid & 31;

    unsigned* barc = &g_barc[g * 32];
    unsigned* genp = &g_gen2[g * 32];
    unsigned mygen = *((volatile unsigned*)genp);

    if (tid == 0) {
        asm volatile("mbarrier.init.shared.b64 [%0], %1;" :: "r"(mbar), "r"(1u) : "memory");
    }

    // --- stage W tile: 64 rows x 64 chunks(16B), fp32 -> fp16 hi/lo, chunk^=(row&7) ---
    #pragma unroll
    for (int i = 0; i < 16; ++i) {
        int gg = tid + i * 256;           // 4096 chunks
        int r = gg >> 6, k16 = gg & 63;
        int j = (r & 3) * 512 + c0 + (r >> 2);
        const float* src = Whh + (size_t)j * 512 + k16 * 8;
        float4 f0 = *(const float4*)(src);
        float4 f1 = *(const float4*)(src + 4);
        uint4 vh, vl;
        vh.x = split_pair_h(f0.x, f0.y, vl.x);
        vh.y = split_pair_h(f0.z, f0.w, vl.y);
        vh.z = split_pair_h(f1.x, f1.y, vl.z);
        vh.w = split_pair_h(f1.z, f1.w, vl.w);
        uint32_t off = (uint32_t)((r << 10) + (((k16 ^ (r & 7))) << 4));
        sts128(wHI + off, vh);
        sts128(wLO + off, vl);
    }

    // --- zero this block's chunks (2ci, 2ci+1) of both images in h-buffer 0 ---
    if (tid < 32) {
        int q = tid & 1, b = (tid >> 1) & 7, img = tid >> 4;
        uint32_t off = (uint32_t)(((g * 2 + img) * 8 + b) * 1024 + (((2 * ci + q) ^ (b & 7)) << 4));
        *(uint4*)((char*)g_h2 + off) = make_uint4(0, 0, 0, 0);
    }
    __syncthreads();

    // GEMM thread mapping: 4m x 2k
    const int wm = wid & 3, wk = wid >> 2;
    const int lrow = lane & 15, lk = lane >> 4;
    const uint32_t arowoff = (uint32_t)(((wm * 16 + lrow) << 10));
    const int ax7 = lrow & 7;

    // --- hoist W-hi fragments (this warp's k-half) into registers ---
    uint32_t AH[16][4];
    #pragma unroll
    for (int ks = 0; ks < 16; ++ks) {
        int ch = (wk * 16 + ks) * 2 + lk;
        uint32_t aoff = (uint32_t)(((ch ^ ax7)) << 4);
        ldmatrix4(AH[ks][0], AH[ks][1], AH[ks][2], AH[ks][3], wHI + arowoff + aoff);
    }

    // --- prologue: prefetch xg(0) + per-group initial barrier ---
    if (tid == 0) {
        asm volatile("mbarrier.arrive.expect_tx.shared.b64 _, [%0], %1;"
                     :: "r"(mbar), "r"(2048u) : "memory");
        asm volatile("cp.async.bulk.shared::cluster.global.mbarrier::complete_tx::bytes "
                     "[%0], [%1], %2, [%3];"
                     :: "r"(xgs_a), "l"((const char*)(xg + (size_t)bx * 512)), "r"(2048u), "r"(mbar) : "memory");
        __threadfence();
        unsigned a = atomicAdd(barc, 1u);
        if (a == GRP - 1u) { *barc = 0u; st_release(genp, mygen + 1u); }
        else { while (ld_acquire(genp) == mygen) {} }
    }
    mygen++;
    __syncthreads();
    MBAR_WAIT(mbar, 0u);

    // B-frag addressing (8 batch rows)
    const int brow = lane & 7;
    const uint32_t browoff = (uint32_t)(brow << 10);
    const int bx7 = brow;
    const int bcs = (lane >> 3) & 1;

    // activation mapping: cl = tid>>3 (0..15), b_local = tid&7  (tid < 128)
    const int cl = tid >> 3;
    const int bb = tid & 7;
    float cst = 0.f;
    // direct-publish address (hi image; lo at +8192) within a 64KB h-buffer
    const uint32_t pub_base = (uint32_t)(((g * 2 + 0) * 8 + bb) * 1024
                                         + (((2 * ci + (cl >> 3)) ^ (bb & 7)) << 4) + (cl & 7) * 2);

    const char* hsrc0 = (const char*)g_h2 + g * 16384;
    const float L2E = 1.4426950408889634f;

    for (int t = 0; t < T_; ++t) {
        // 1. bulk copies from h-buffer t&1: h hi+lo (16KB) + xg(t+1) (2KB)
        if (tid == 0) {
            unsigned txb = 16384u + ((t + 1 < T_) ? 2048u : 0u);
            asm volatile("mbarrier.arrive.expect_tx.shared.b64 _, [%0], %1;"
                         :: "r"(mbar), "r"(txb) : "memory");
            asm volatile("cp.async.bulk.shared::cluster.global.mbarrier::complete_tx::bytes "
                         "[%0], [%1], %2, [%3];"
                         :: "r"(bHI), "l"(hsrc0 + (size_t)(t & 1) * 65536), "r"(16384u), "r"(mbar) : "memory");
            if (t + 1 < T_) {
                const char* xsrc = (const char*)(xg + (((size_t)(t + 1) * NBLK + bx) * 512));
                asm volatile("cp.async.bulk.shared::cluster.global.mbarrier::complete_tx::bytes "
                             "[%0], [%1], %2, [%3];"
                             :: "r"(xgs_a + (((t + 1) & 1) ? 2048u : 0u)), "l"(xsrc), "r"(2048u), "r"(mbar) : "memory");
            }
        }
        MBAR_WAIT(mbar, (uint32_t)((t + 1) & 1));

        // 2. GEMM: 16 k-steps (this warp's half), 3 accumulator chains
        float acc_a[4] = {0.f, 0.f, 0.f, 0.f};
        float acc_b[4] = {0.f, 0.f, 0.f, 0.f};
        float acc_c[4] = {0.f, 0.f, 0.f, 0.f};
        #pragma unroll
        for (int ks = 0; ks < 16; ++ks) {
            int chA = (wk * 16 + ks) * 2 + lk;
            int chB = (wk * 16 + ks) * 2 + bcs;
            uint32_t aoff = (uint32_t)(((chA ^ ax7)) << 4);
            uint32_t boff = (uint32_t)(((chB ^ bx7)) << 4);
            uint32_t al0, al1, al2, al3;
            uint32_t bh0, bh1, bl0, bl1;
            ldmatrix4(al0, al1, al2, al3, wLO + arowoff + aoff);
            ldmatrix2(bh0, bh1, bHI + browoff + boff);
            ldmatrix2(bl0, bl1, (bHI + 8192u) + browoff + boff);
            mma16816h(acc_a, AH[ks], bh0, bh1);
            mma16816h(acc_b, AH[ks], bl0, bl1);
            uint32_t alr[4] = {al0, al1, al2, al3};
            mma16816h(acc_c, alr, bh0, bh1);
        }

        // 3. combine + store per-k-half gates to gsm[wk] ([64][10])
        {
            int r0 = wm * 16 + (lane >> 2);
            int cb = (lane & 3) * 2;
            float* gk = gsm + wk * 640;
            float s0 = acc_a[0] + acc_b[0] + acc_c[0];
            float s1 = acc_a[1] + acc_b[1] + acc_c[1];
            float s2 = acc_a[2] + acc_b[2] + acc_c[2];
            float s3 = acc_a[3] + acc_b[3] + acc_c[3];
            *(float2*)&gk[r0 * 10 + cb]       = make_float2(s0, s1);
            *(float2*)&gk[(r0 + 8) * 10 + cb] = make_float2(s2, s3);
        }
        __syncthreads();

        // 4. activation (MUFU-minimized) + DIRECT publish into h-buffer (t+1)&1
        if (tid < 128) {
            const float* xb2 = xgs + ((t & 1) ? 512 : 0) + bb * 64;
            int r = cl * 4;
            float gi = gsm[(r + 0) * 10 + bb] + gsm[640 + (r + 0) * 10 + bb] + xb2[cl];
            float gf = gsm[(r + 1) * 10 + bb] + gsm[640 + (r + 1) * 10 + bb] + xb2[16 + cl];
            float gg = gsm[(r + 2) * 10 + bb] + gsm[640 + (r + 2) * 10 + bb] + xb2[32 + cl];
            float go = gsm[(r + 3) * 10 + bb] + gsm[640 + (r + 3) * 10 + bb] + xb2[48 + cl];

            float xi = fminf(fmaxf(gi, -15.f), 15.f);
            float xf = fminf(fmaxf(gf, -15.f), 15.f);
            float xgc = fminf(fmaxf(gg, -7.5f), 7.5f);
            float ea = exp2f(-xi * L2E);
            float eb = exp2f(-xf * L2E);
            float eu = exp2f(xgc * (2.f * L2E));
            float aa = 1.f + ea, bbv = 1.f + eb, uu = 1.f + eu;
            float p2 = aa * bbv;
            float r3 = rcp_fast(p2 * uu);
            float inv_u = r3 * p2;
            float r2 = r3 * uu;
            float iv = r2 * bbv;
            float fv = r2 * aa;
            float gv = 1.f - 2.f * inv_u;
            cst = fv * cst + iv * gv;

            float xo = fminf(fmaxf(go, -15.f), 15.f);
            float xc = fminf(fmaxf(cst, -7.5f), 7.5f);
            float ed = exp2f(-xo * L2E);
            float ev = exp2f(xc * (2.f * L2E));
            float dd = 1.f + ed, vv = 1.f + ev;
            float rq = rcp_fast(dd * vv);
            float inv_v = rq * dd;
            float ov = rq * vv;
            float hv = ov * (1.f - 2.f * inv_v);

            __half hh = __float2half_rn(hv);
            __half hl = __float2half_rn(hv - __half2float(hh));
            char* pb = (char*)g_h2 + (size_t)((t + 1) & 1) * 65536 + pub_base;
            *(__half*)pb = hh;
            *(__half*)(pb + 8192) = hl;
            Y[((size_t)(g * 8 + bb) * T_ + t) * H_ + c0 + cl] = hv;
        }

        // 5. per-group grid barrier
        __syncthreads();
        if (tid == 0) {
            __threadfence();
            unsigned a = atomicAdd(barc, 1u);
            if (a == GRP - 1u) { *barc = 0u; st_release(genp, mygen + 1u); }
            else { while (ld_acquire(genp) == mygen) {} }
        }
        mygen++;
        __syncthreads();
    }
}

// ---------------------------------------------------------------------------
// mean over T + head GEMV
// ---------------------------------------------------------------------------
__global__ void pool_head_kernel(const float* __restrict__ head_w,
                                 const float* __restrict__ head_b,
                                 float* __restrict__ out) {
    int b = blockIdx.x;
    int h = threadIdx.x;
    __shared__ float feat[H_];
    const float* Yp = g_bufB + (size_t)b * T_ * H_;
    float s = 0.f;
    for (int t = 0; t < T_; ++t) s += Yp[t * H_ + h];
    feat[h] = s * (1.0f / (float)T_);
    __syncthreads();
    for (int cc = threadIdx.x; cc < NCLS; cc += blockDim.x) {
        float a = head_b[cc];
        const float* wr = head_w + cc * H_;
        for (int k = 0; k < H_; ++k) a += feat[k] * wr[k];
        out[b * NCLS + cc] = a;
    }
}

// ---------------------------------------------------------------------------
extern "C" void kernel_launch(void* const* d_in, const int* in_sizes, int n_in,
                              void* d_out, int out_size) {
    const float* x     = (const float*)d_in[0];
    const float* convw = (const float*)d_in[1];
    const float* gamma = (const float*)d_in[2];
    const float* beta  = (const float*)d_in[3];

    bool head_first = (in_sizes[4] == NCLS * H_);
    int o = head_first ? 6 : 4;
    const float* headw = (const float*)d_in[head_first ? 4 : 13];
    const float* headb = (const float*)d_in[head_first ? 5 : 14];
    const float* wih[3] = { (const float*)d_in[o + 0], (const float*)d_in[o + 3], (const float*)d_in[o + 6] };
    const float* whh[3] = { (const float*)d_in[o + 1], (const float*)d_in[o + 4], (const float*)d_in[o + 7] };
    const float* bb[3]  = { (const float*)d_in[o + 2], (const float*)d_in[o + 5], (const float*)d_in[o + 8] };

    static int smem_set = 0;
    if (!smem_set) {
        cudaFuncSetAttribute(lstm_kernel, cudaFuncAttributeMaxDynamicSharedMemorySize, SMEM_REQ);
        cudaFuncSetAttribute(xg_hmma_kernel, cudaFuncAttributeMaxDynamicSharedMemorySize, XG_SMEM_REQ);
        smem_set = 1;
    }

    void* xgsym = nullptr;   cudaGetSymbolAddress(&xgsym, g_xg);
    void* bufAsym = nullptr; cudaGetSymbolAddress(&bufAsym, g_bufA);
    void* bufBsym = nullptr; cudaGetSymbolAddress(&bufBsym, g_bufB);

    conv_kernel<<<B_ * NF, 128>>>(x, convw);
    gn_kernel<<<B_ * GN_G, 256>>>(gamma, beta);

    for (int layer = 1; layer <= 3; ++layer) {
        int din = (layer == 1) ? NF : H_;
        dim3 gg(G4H / 128, (B_ * T_) / 128);
        xg_hmma_kernel<<<gg, 256, XG_SMEM_REQ>>>(layer, wih[layer - 1], bb[layer - 1], din);
        float* yptr = (layer == 2) ? (float*)bufAsym : (float*)bufBsym;
        lstm_kernel<<<NBLK, THR, SMEM_REQ>>>(whh[layer - 1], (const float*)xgsym, yptr);
    }

    pool_head_kernel<<<B_, H_>>>(headw, headb, (float*)d_out);
}